// round 2
// baseline (speedup 1.0000x reference)
#include <cuda_runtime.h>
#include <cstdint>

#define BATCH 2
#define SEQ   2048
#define NTOK  (BATCH * SEQ)
#define DM    1024
#define NC    3584

#define COL_QSA 0
#define COL_KSA 512
#define COL_VSA 1024
#define COL_QA  1536
#define COL_KA  2048
#define COL_QR  2560
#define COL_KR  3072

// Scratch (allocation-free rule: __device__ globals)
__device__ float g_proj[NTOK * NC];    // 7 fused projections of x
__device__ float g_sv  [NTOK * 512];   // symbols @ wv_ra^T
__device__ float g_sa  [NTOK * 512];   // SA context
__device__ float g_ra  [NTOK * 512];   // RA context (sym + rel_out)

struct W8 { const float* p[7]; };

// ---------------------------------------------------------------------------
// Generic SGEMM:  C[M, N] = A[M, K] @ W^T   (W selected per 512-col block)
// BM=BN=128, BK=16, 256 threads, 8x8 per thread.
// ---------------------------------------------------------------------------
__global__ void __launch_bounds__(256) sgemm_wt(
    const float* __restrict__ A, W8 w, float* __restrict__ C,
    int K, int ldC, int cOff)
{
    __shared__ float As[16][128];
    __shared__ float Bs[16][128];

    const int tid   = threadIdx.x;
    const int mBase = blockIdx.y * 128;
    const int nBase = blockIdx.x * 128;
    const float* Wm = w.p[nBase >> 9];
    const int wrow  = nBase & 511;

    const int trow = (tid >> 4) * 8;
    const int tcol = (tid & 15) * 8;

    float acc[8][8];
    #pragma unroll
    for (int i = 0; i < 8; i++)
        #pragma unroll
        for (int j = 0; j < 8; j++) acc[i][j] = 0.f;

    for (int k0 = 0; k0 < K; k0 += 16) {
        #pragma unroll
        for (int u = 0; u < 2; u++) {
            int s  = tid + u * 256;      // 512 float4 slots
            int m  = s >> 2;
            int kq = s & 3;
            float4 va = *(const float4*)(A + (mBase + m) * K + k0 + kq * 4);
            As[kq*4+0][m] = va.x; As[kq*4+1][m] = va.y;
            As[kq*4+2][m] = va.z; As[kq*4+3][m] = va.w;
            float4 vb = *(const float4*)(Wm + (wrow + m) * K + k0 + kq * 4);
            Bs[kq*4+0][m] = vb.x; Bs[kq*4+1][m] = vb.y;
            Bs[kq*4+2][m] = vb.z; Bs[kq*4+3][m] = vb.w;
        }
        __syncthreads();

        #pragma unroll
        for (int kk = 0; kk < 16; kk++) {
            float ra[8], rb[8];
            #pragma unroll
            for (int i = 0; i < 8; i++) ra[i] = As[kk][trow + i];
            #pragma unroll
            for (int j = 0; j < 8; j++) rb[j] = Bs[kk][tcol + j];
            #pragma unroll
            for (int i = 0; i < 8; i++)
                #pragma unroll
                for (int j = 0; j < 8; j++)
                    acc[i][j] += ra[i] * rb[j];
        }
        __syncthreads();
    }

    #pragma unroll
    for (int i = 0; i < 8; i++) {
        float* dst = C + (mBase + trow + i) * ldC + cOff + nBase + tcol;
        *(float4*)(dst + 0) = make_float4(acc[i][0], acc[i][1], acc[i][2], acc[i][3]);
        *(float4*)(dst + 4) = make_float4(acc[i][4], acc[i][5], acc[i][6], acc[i][7]);
    }
}

// ---------------------------------------------------------------------------
// RoPE in-place on proj columns [0,1024) (q_sa,k_sa) and [1536,2560) (qa,ka)
// interleaved pairs within each 64-dim head.
// ---------------------------------------------------------------------------
__global__ void rope_kernel(const float* __restrict__ fc, const float* __restrict__ fs)
{
    int idx = blockIdx.x * blockDim.x + threadIdx.x;   // NTOK * 1024 pairs
    int token  = idx >> 10;
    int p      = idx & 1023;
    int range  = p >> 9;
    int within = p & 511;
    int col0   = (range ? 1536 : 0) + within * 2;
    int t      = within & 31;          // rotation index within 64-dim head
    int s_idx  = token & (SEQ - 1);

    float c  = fc[s_idx * 32 + t];
    float sn = fs[s_idx * 32 + t];
    float* ptr = g_proj + token * NC + col0;
    float x0 = ptr[0], x1 = ptr[1];
    ptr[0] = x0 * c - x1 * sn;
    ptr[1] = x0 * sn + x1 * c;
}

// ---------------------------------------------------------------------------
// SA causal flash attention, per (b,h). Br=64, Bc=64, 256 threads (4/row).
// ---------------------------------------------------------------------------
#define SA_SMEM ((64*65*3 + 64*64) * 4)

__global__ void __launch_bounds__(256) sa_flash_kernel()
{
    extern __shared__ float sm[];
    float* sQ = sm;                 // [64][65]
    float* sK = sm + 64*65;         // [64][65]
    float* sP = sm + 2*64*65;       // [64][65]
    float* sV = sm + 3*64*65;       // [64][64]

    const int tid  = threadIdx.x;
    const int row  = tid >> 2;
    const int lane = tid & 3;
    const int b    = blockIdx.y >> 3;
    const int h    = blockIdx.y & 7;
    const int i0   = blockIdx.x * 64;
    const int tbase = b * SEQ + i0;

    #pragma unroll
    for (int u = 0; u < 16; u++) {
        int e = tid + u * 256;
        int rr = e >> 6, dd = e & 63;
        sQ[rr*65 + dd] = g_proj[(tbase + rr) * NC + COL_QSA + h*64 + dd];
    }

    float m = -1e30f, l = 0.f;
    float acc[16];
    #pragma unroll
    for (int t = 0; t < 16; t++) acc[t] = 0.f;

    const int nJT = blockIdx.x + 1;
    for (int jt = 0; jt < nJT; jt++) {
        __syncthreads();
        const int jb = b * SEQ + jt * 64;
        #pragma unroll
        for (int u = 0; u < 16; u++) {
            int e = tid + u * 256;
            int rr = e >> 6, dd = e & 63;
            sK[rr*65 + dd] = g_proj[(jb + rr) * NC + COL_KSA + h*64 + dd];
            sV[rr*64 + dd] = g_proj[(jb + rr) * NC + COL_VSA + h*64 + dd];
        }
        __syncthreads();

        const bool diag = (jt == blockIdx.x);
        float sc[16], lmax = -1e30f;
        #pragma unroll
        for (int jj = 0; jj < 16; jj++) {
            int j = jj * 4 + lane;
            float s = 0.f;
            #pragma unroll
            for (int kk = 0; kk < 64; kk++)
                s += sQ[row*65 + kk] * sK[j*65 + kk];
            s *= 0.125f;
            if (diag && j > row) s = -1e30f;
            sc[jj] = s;
            lmax = fmaxf(lmax, s);
        }
        lmax = fmaxf(lmax, __shfl_xor_sync(0xffffffffu, lmax, 1));
        lmax = fmaxf(lmax, __shfl_xor_sync(0xffffffffu, lmax, 2));
        float newm = fmaxf(m, lmax);
        float corr = __expf(m - newm);
        float ls = 0.f;
        #pragma unroll
        for (int jj = 0; jj < 16; jj++) {
            float p = __expf(sc[jj] - newm);
            sP[row*65 + jj*4 + lane] = p;
            ls += p;
        }
        ls += __shfl_xor_sync(0xffffffffu, ls, 1);
        ls += __shfl_xor_sync(0xffffffffu, ls, 2);
        l = l * corr + ls;
        m = newm;
        #pragma unroll
        for (int t = 0; t < 16; t++) acc[t] *= corr;
        __syncwarp();

        #pragma unroll 4
        for (int jj2 = 0; jj2 < 64; jj2++) {
            float pj = sP[row*65 + jj2];
            #pragma unroll
            for (int t = 0; t < 16; t++)
                acc[t] += pj * sV[jj2*64 + lane + 4*t];
        }
    }

    float invl = 1.f / l;
    const int token = tbase + row;
    #pragma unroll
    for (int t = 0; t < 16; t++)
        g_sa[token*512 + h*64 + lane + 4*t] = acc[t] * invl;
}

// ---------------------------------------------------------------------------
// RA flash attention with extended V = [sv(64) | kr(512)] (d_v = 576), per
// (b,h). Br=64, Bc=32, 512 threads (8/row). Epilogue computes
// attended_rel[r] = rel_scale * qr[i,r,:]·attkr[r,:] and rel_out via wr.
// ---------------------------------------------------------------------------
#define RA_SMEM ((64*65 + 32*65 + 64*33 + 32*576) * 4)

__global__ void __launch_bounds__(512) ra_flash_kernel(const float* __restrict__ wr)
{
    extern __shared__ float sm[];
    float* sQ = sm;                          // [64][65]
    float* sK = sQ + 64*65;                  // [32][65]
    float* sP = sK + 32*65;                  // [64][33]
    float* sV = sP + 64*33;                  // [32][576]

    const int tid  = threadIdx.x;
    const int row  = tid >> 3;
    const int lane = tid & 7;
    const int b    = blockIdx.y >> 3;
    const int h    = blockIdx.y & 7;
    const int i0   = blockIdx.x * 64;
    const int tbase = b * SEQ + i0;

    #pragma unroll
    for (int u = 0; u < 8; u++) {
        int e = tid + u * 512;
        int rr = e >> 6, dd = e & 63;
        sQ[rr*65 + dd] = g_proj[(tbase + rr) * NC + COL_QA + h*64 + dd];
    }

    float m = -1e30f, l = 0.f;
    float acc[72];
    #pragma unroll
    for (int t = 0; t < 72; t++) acc[t] = 0.f;

    const int nJT = 2 * blockIdx.x + 2;
    for (int jt = 0; jt < nJT; jt++) {
        __syncthreads();
        const int j0 = jt * 32;
        const int jb = b * SEQ + j0;
        #pragma unroll
        for (int u = 0; u < 4; u++) {
            int e = tid + u * 512;
            int rr = e >> 6, dd = e & 63;
            sK[rr*65 + dd] = g_proj[(jb + rr) * NC + COL_KA + h*64 + dd];
        }
        for (int e = tid; e < 32 * 576; e += 512) {
            int rr = e / 576;
            int dd = e - rr * 576;
            float v;
            if (dd < 64) v = g_sv[(jb + rr) * 512 + h*64 + dd];
            else         v = g_proj[(jb + rr) * NC + COL_KR + dd - 64];
            sV[e] = v;
        }
        __syncthreads();

        float sc[4], lmax = -1e30f;
        #pragma unroll
        for (int jj = 0; jj < 4; jj++) {
            int j = lane * 4 + jj;
            float s = 0.f;
            #pragma unroll
            for (int kk = 0; kk < 64; kk++)
                s += sQ[row*65 + kk] * sK[j*65 + kk];
            s *= 0.125f;
            if (j0 + j > i0 + row) s = -1e30f;
            sc[jj] = s;
            lmax = fmaxf(lmax, s);
        }
        lmax = fmaxf(lmax, __shfl_xor_sync(0xffffffffu, lmax, 1));
        lmax = fmaxf(lmax, __shfl_xor_sync(0xffffffffu, lmax, 2));
        lmax = fmaxf(lmax, __shfl_xor_sync(0xffffffffu, lmax, 4));
        float newm = fmaxf(m, lmax);
        float corr = __expf(m - newm);
        float ls = 0.f;
        #pragma unroll
        for (int jj = 0; jj < 4; jj++) {
            float p = __expf(sc[jj] - newm);
            sP[row*33 + lane*4 + jj] = p;
            ls += p;
        }
        ls += __shfl_xor_sync(0xffffffffu, ls, 1);
        ls += __shfl_xor_sync(0xffffffffu, ls, 2);
        ls += __shfl_xor_sync(0xffffffffu, ls, 4);
        l = l * corr + ls;
        m = newm;
        #pragma unroll
        for (int t = 0; t < 72; t++) acc[t] *= corr;
        __syncwarp();

        #pragma unroll 4
        for (int jj2 = 0; jj2 < 32; jj2++) {
            float pj = sP[row*33 + jj2];
            #pragma unroll
            for (int t = 0; t < 72; t++)
                acc[t] += pj * sV[jj2*576 + lane + 8*t];
        }
    }

    const float invl = 1.f / l;
    const int token = tbase + row;

    // attended_rel[r] = rel_scale * sum_dd qr[token][r*64+dd] * attkr[dd]
    const float* qr = g_proj + token * NC + COL_QR;
    float attrel[8];
    #pragma unroll
    for (int r = 0; r < 8; r++) {
        float pr = 0.f;
        #pragma unroll
        for (int u = 0; u < 8; u++)
            pr += qr[r*64 + 8*u + lane] * acc[8 + 8*r + u];
        pr += __shfl_xor_sync(0xffffffffu, pr, 1);
        pr += __shfl_xor_sync(0xffffffffu, pr, 2);
        pr += __shfl_xor_sync(0xffffffffu, pr, 4);
        attrel[r] = pr * invl * 0.125f;
    }

    // ra_ctx = attended_sym + sum_r attrel[r] * wr[h][d][r]
    #pragma unroll
    for (int t = 0; t < 8; t++) {
        int d = lane + 8*t;
        float ro = 0.f;
        #pragma unroll
        for (int r = 0; r < 8; r++)
            ro += attrel[r] * wr[h*512 + d*8 + r];
        g_ra[token*512 + h*64 + d] = acc[t] * invl + ro;
    }
}

// ---------------------------------------------------------------------------
extern "C" void kernel_launch(void* const* d_in, const int* in_sizes, int n_in,
                              void* d_out, int out_size)
{
    (void)in_sizes; (void)n_in; (void)out_size;
    const float* x      = (const float*)d_in[0];
    const float* symb   = (const float*)d_in[1];
    const float* fc     = (const float*)d_in[2];
    const float* fs     = (const float*)d_in[3];
    const float* wq_sa  = (const float*)d_in[4];
    const float* wk_sa  = (const float*)d_in[5];
    const float* wv_sa  = (const float*)d_in[6];
    const float* wo_sa  = (const float*)d_in[7];
    const float* wq_at  = (const float*)d_in[8];
    const float* wk_at  = (const float*)d_in[9];
    const float* wq_rel = (const float*)d_in[10];
    const float* wk_rel = (const float*)d_in[11];
    const float* wr     = (const float*)d_in[12];
    const float* wv_ra  = (const float*)d_in[13];
    const float* wo_ra  = (const float*)d_in[14];
    float* out = (float*)d_out;

    float *proj, *svb, *sab, *rab;
    cudaGetSymbolAddress((void**)&proj, g_proj);
    cudaGetSymbolAddress((void**)&svb,  g_sv);
    cudaGetSymbolAddress((void**)&sab,  g_sa);
    cudaGetSymbolAddress((void**)&rab,  g_ra);

    cudaFuncSetAttribute(sa_flash_kernel, cudaFuncAttributeMaxDynamicSharedMemorySize, SA_SMEM);
    cudaFuncSetAttribute(ra_flash_kernel, cudaFuncAttributeMaxDynamicSharedMemorySize, RA_SMEM);

    // 1) fused projections of x: [q_sa|k_sa|v_sa|qa|ka|qr|kr]
    W8 w7;
    w7.p[0] = wq_sa; w7.p[1] = wk_sa; w7.p[2] = wv_sa;
    w7.p[3] = wq_at; w7.p[4] = wk_at; w7.p[5] = wq_rel; w7.p[6] = wk_rel;
    sgemm_wt<<<dim3(NC/128, NTOK/128), 256>>>(x, w7, proj, DM, NC, 0);

    // 2) sv = symbols @ wv_ra^T
    W8 wv; for (int i = 0; i < 7; i++) wv.p[i] = wv_ra;
    sgemm_wt<<<dim3(4, NTOK/128), 256>>>(symb, wv, svb, DM, 512, 0);

    // 3) RoPE on q_sa,k_sa,qa,ka
    rope_kernel<<<(NTOK * 1024) / 256, 256>>>(fc, fs);

    // 4) SA flash
    sa_flash_kernel<<<dim3(SEQ/64, BATCH*8), 256, SA_SMEM>>>();

    // 5) RA flash (with fused rel epilogue)
    ra_flash_kernel<<<dim3(SEQ/64, BATCH*8), 512, RA_SMEM>>>(wr);

    // 6) output projections into concatenated out
    W8 wo1; for (int i = 0; i < 7; i++) wo1.p[i] = wo_sa;
    sgemm_wt<<<dim3(4, NTOK/128), 256>>>(sab, wo1, out, 512, 1024, 0);
    W8 wo2; for (int i = 0; i < 7; i++) wo2.p[i] = wo_ra;
    sgemm_wt<<<dim3(4, NTOK/128), 256>>>(rab, wo2, out, 512, 1024, 512);
}

// round 5
// speedup vs baseline: 2.2811x; 2.2811x over previous
#include <cuda_runtime.h>
#include <cstdint>

#define BATCH 2
#define SEQ   2048
#define NTOK  (BATCH * SEQ)
#define DM    1024
#define NC    3584

#define COL_QSA 0
#define COL_KSA 512
#define COL_VSA 1024
#define COL_QA  1536
#define COL_KA  2048
#define COL_QR  2560
#define COL_KR  3072

// Scratch (allocation-free rule: __device__ globals)
__device__ float g_proj[NTOK * NC];    // 7 fused projections of x
__device__ float g_sv  [NTOK * 512];   // symbols @ wv_ra^T
__device__ float g_sa  [NTOK * 512];   // SA context
__device__ float g_ra  [NTOK * 512];   // RA context (sym + rel_out)

struct W8 { const float* p[7]; };

// ---------------------------------------------------------------------------
// tf32 helpers
// ---------------------------------------------------------------------------
__device__ __forceinline__ float to_tf32(float x) {
    uint32_t u;
    asm("cvt.rna.tf32.f32 %0, %1;" : "=r"(u) : "f"(x));
    return __uint_as_float(u);
}
__device__ __forceinline__ float4 f4_tf32(float4 v) {
    return make_float4(to_tf32(v.x), to_tf32(v.y), to_tf32(v.z), to_tf32(v.w));
}
__device__ __forceinline__ void mma_tf32(float* d, const float* a, const float* b) {
    asm volatile(
        "mma.sync.aligned.m16n8k8.row.col.f32.tf32.tf32.f32 "
        "{%0,%1,%2,%3}, {%4,%5,%6,%7}, {%8,%9}, {%0,%1,%2,%3};"
        : "+f"(d[0]), "+f"(d[1]), "+f"(d[2]), "+f"(d[3])
        : "r"(__float_as_uint(a[0])), "r"(__float_as_uint(a[1])),
          "r"(__float_as_uint(a[2])), "r"(__float_as_uint(a[3])),
          "r"(__float_as_uint(b[0])), "r"(__float_as_uint(b[1])));
}

// ---------------------------------------------------------------------------
// tf32 tensor-core GEMM:  C[M,N] = A[M,K] @ W^T   (W row-major [N,K], selected
// per 512-col block). BM=BN=128, BK=32, 256 threads / 8 warps (2x4).
// Warp tile 64x32 = 4x4 mma tiles of m16n8k8.
// ---------------------------------------------------------------------------
__global__ void __launch_bounds__(256) gemm_tf32(
    const float* __restrict__ A, W8 w, float* __restrict__ C,
    int K, int ldC, int cOff)
{
    __shared__ float As[128][36];
    __shared__ float Bs[128][36];

    const int tid   = threadIdx.x;
    const int lane  = tid & 31;
    const int wid   = tid >> 5;
    const int warpM = wid >> 2;        // 0..1
    const int warpN = wid & 3;         // 0..3
    const int g     = lane >> 2;       // 0..7
    const int tig   = lane & 3;        // 0..3

    const int mBase = blockIdx.y * 128;
    const int nBase = blockIdx.x * 128;
    const float* Wm = w.p[nBase >> 9];
    const int wrow  = nBase & 511;

    const float* Aptr = A  + (size_t)mBase * K;
    const float* Bptr = Wm + (size_t)wrow  * K;

    float acc[4][4][4];
    #pragma unroll
    for (int mi = 0; mi < 4; mi++)
        #pragma unroll
        for (int ni = 0; ni < 4; ni++)
            #pragma unroll
            for (int c = 0; c < 4; c++) acc[mi][ni][c] = 0.f;

    const int nT = K >> 5;
    float4 pa[4], pb[4];
    #pragma unroll
    for (int u = 0; u < 4; u++) {
        int s_ = tid + (u << 8);
        int r = s_ >> 3, q = s_ & 7;
        pa[u] = *(const float4*)(Aptr + (size_t)r * K + q * 4);
        pb[u] = *(const float4*)(Bptr + (size_t)r * K + q * 4);
    }

    for (int t = 0; t < nT; t++) {
        #pragma unroll
        for (int u = 0; u < 4; u++) {
            int s_ = tid + (u << 8);
            int r = s_ >> 3, q = s_ & 7;
            *(float4*)&As[r][q * 4] = f4_tf32(pa[u]);
            *(float4*)&Bs[r][q * 4] = f4_tf32(pb[u]);
        }
        __syncthreads();

        if (t + 1 < nT) {
            int k0 = (t + 1) << 5;
            #pragma unroll
            for (int u = 0; u < 4; u++) {
                int s_ = tid + (u << 8);
                int r = s_ >> 3, q = s_ & 7;
                pa[u] = *(const float4*)(Aptr + (size_t)r * K + k0 + q * 4);
                pb[u] = *(const float4*)(Bptr + (size_t)r * K + k0 + q * 4);
            }
        }

        #pragma unroll
        for (int ks = 0; ks < 4; ks++) {
            float a[4][4], b[4][2];
            const int kc = ks * 8 + tig;
            #pragma unroll
            for (int mi = 0; mi < 4; mi++) {
                int r0 = warpM * 64 + mi * 16 + g;
                a[mi][0] = As[r0][kc];
                a[mi][1] = As[r0 + 8][kc];
                a[mi][2] = As[r0][kc + 4];
                a[mi][3] = As[r0 + 8][kc + 4];
            }
            #pragma unroll
            for (int ni = 0; ni < 4; ni++) {
                int c0 = warpN * 32 + ni * 8 + g;
                b[ni][0] = Bs[c0][kc];
                b[ni][1] = Bs[c0][kc + 4];
            }
            #pragma unroll
            for (int mi = 0; mi < 4; mi++)
                #pragma unroll
                for (int ni = 0; ni < 4; ni++)
                    mma_tf32(acc[mi][ni], a[mi], b[ni]);
        }
        __syncthreads();
    }

    #pragma unroll
    for (int mi = 0; mi < 4; mi++) {
        int row = mBase + warpM * 64 + mi * 16 + g;
        #pragma unroll
        for (int ni = 0; ni < 4; ni++) {
            int col = cOff + nBase + warpN * 32 + ni * 8 + tig * 2;
            *(float2*)&C[(size_t)row * ldC + col] =
                make_float2(acc[mi][ni][0], acc[mi][ni][1]);
            *(float2*)&C[(size_t)(row + 8) * ldC + col] =
                make_float2(acc[mi][ni][2], acc[mi][ni][3]);
        }
    }
}

// ---------------------------------------------------------------------------
// RoPE in-place (unchanged, known correct)
// ---------------------------------------------------------------------------
__global__ void rope_kernel(const float* __restrict__ fc, const float* __restrict__ fs)
{
    int idx = blockIdx.x * blockDim.x + threadIdx.x;
    int token  = idx >> 10;
    int p      = idx & 1023;
    int range  = p >> 9;
    int within = p & 511;
    int col0   = (range ? 1536 : 0) + within * 2;
    int t      = within & 31;
    int s_idx  = token & (SEQ - 1);

    float c  = fc[s_idx * 32 + t];
    float sn = fs[s_idx * 32 + t];
    float* ptr = g_proj + (size_t)token * NC + col0;
    float x0 = ptr[0], x1 = ptr[1];
    ptr[0] = x0 * c - x1 * sn;
    ptr[1] = x0 * sn + x1 * c;
}

// ---------------------------------------------------------------------------
// SA causal flash v2: Br=64, Bc=64, 256 threads as (ty 0..15) x (tx 0..15),
// each thread a 4x4 score tile and 4x4 output tile. float4 smem access.
// ---------------------------------------------------------------------------
#define SA2_SMEM (4 * 64 * 68 * 4)

__global__ void __launch_bounds__(256) sa_flash2()
{
    extern __shared__ float sm[];
    float* sQt = sm;                // [k][i] stride 68
    float* sKt = sm + 64 * 68;      // [k][j] stride 68
    float* sV  = sm + 2 * 64 * 68;  // [j][d] stride 68
    float* sP  = sm + 3 * 64 * 68;  // [i][j] stride 68

    const int tid = threadIdx.x;
    const int tx  = tid & 15;
    const int ty  = tid >> 4;
    const int b   = blockIdx.y >> 3;
    const int h   = blockIdx.y & 7;
    const int i0  = blockIdx.x * 64;
    const int tbase = b * SEQ + i0;

    // load Q transposed
    #pragma unroll
    for (int u = 0; u < 4; u++) {
        int e = tid + (u << 8);
        int rr = e >> 4, d4 = e & 15;
        float4 q = *(const float4*)(g_proj + (size_t)(tbase + rr) * NC + COL_QSA + h * 64 + d4 * 4);
        sQt[(d4 * 4 + 0) * 68 + rr] = q.x;
        sQt[(d4 * 4 + 1) * 68 + rr] = q.y;
        sQt[(d4 * 4 + 2) * 68 + rr] = q.z;
        sQt[(d4 * 4 + 3) * 68 + rr] = q.w;
    }

    float mst[4], l[4], o[4][4];
    #pragma unroll
    for (int ii = 0; ii < 4; ii++) {
        mst[ii] = -1e30f; l[ii] = 0.f;
        #pragma unroll
        for (int dd = 0; dd < 4; dd++) o[ii][dd] = 0.f;
    }

    const int nJT = blockIdx.x + 1;
    for (int jt = 0; jt < nJT; jt++) {
        __syncthreads();
        const int jb = b * SEQ + jt * 64;
        #pragma unroll
        for (int u = 0; u < 4; u++) {
            int e = tid + (u << 8);
            int rr = e >> 4, d4 = e & 15;
            const float* base = g_proj + (size_t)(jb + rr) * NC + h * 64;
            float4 kv = *(const float4*)(base + COL_KSA + d4 * 4);
            sKt[(d4 * 4 + 0) * 68 + rr] = kv.x;
            sKt[(d4 * 4 + 1) * 68 + rr] = kv.y;
            sKt[(d4 * 4 + 2) * 68 + rr] = kv.z;
            sKt[(d4 * 4 + 3) * 68 + rr] = kv.w;
            float4 vv = *(const float4*)(base + COL_VSA + d4 * 4);
            *(float4*)&sV[rr * 68 + d4 * 4] = vv;
        }
        __syncthreads();

        float s[4][4];
        #pragma unroll
        for (int ii = 0; ii < 4; ii++)
            #pragma unroll
            for (int jj = 0; jj < 4; jj++) s[ii][jj] = 0.f;

        #pragma unroll 4
        for (int k = 0; k < 64; k++) {
            float4 q = *(const float4*)&sQt[k * 68 + 4 * ty];
            float4 kk = *(const float4*)&sKt[k * 68 + 4 * tx];
            s[0][0] += q.x * kk.x; s[0][1] += q.x * kk.y; s[0][2] += q.x * kk.z; s[0][3] += q.x * kk.w;
            s[1][0] += q.y * kk.x; s[1][1] += q.y * kk.y; s[1][2] += q.y * kk.z; s[1][3] += q.y * kk.w;
            s[2][0] += q.z * kk.x; s[2][1] += q.z * kk.y; s[2][2] += q.z * kk.z; s[2][3] += q.z * kk.w;
            s[3][0] += q.w * kk.x; s[3][1] += q.w * kk.y; s[3][2] += q.w * kk.z; s[3][3] += q.w * kk.w;
        }

        float rmax[4], ls[4], corr[4];
        #pragma unroll
        for (int ii = 0; ii < 4; ii++) {
            int i_g = i0 + 4 * ty + ii;
            rmax[ii] = -1e30f;
            #pragma unroll
            for (int jj = 0; jj < 4; jj++) {
                int j_g = jt * 64 + 4 * tx + jj;
                s[ii][jj] = (j_g <= i_g) ? s[ii][jj] * 0.125f : -1e30f;
                rmax[ii] = fmaxf(rmax[ii], s[ii][jj]);
            }
        }
        #pragma unroll
        for (int st = 8; st >= 1; st >>= 1)
            #pragma unroll
            for (int ii = 0; ii < 4; ii++)
                rmax[ii] = fmaxf(rmax[ii], __shfl_xor_sync(0xffffffffu, rmax[ii], st));
        #pragma unroll
        for (int ii = 0; ii < 4; ii++) {
            float nm = fmaxf(mst[ii], rmax[ii]);
            corr[ii] = __expf(mst[ii] - nm);
            mst[ii] = nm;
            float lsum = 0.f;
            #pragma unroll
            for (int jj = 0; jj < 4; jj++) {
                float p = __expf(s[ii][jj] - nm);
                s[ii][jj] = p;
                lsum += p;
            }
            ls[ii] = lsum;
        }
        #pragma unroll
        for (int st = 8; st >= 1; st >>= 1)
            #pragma unroll
            for (int ii = 0; ii < 4; ii++)
                ls[ii] += __shfl_xor_sync(0xffffffffu, ls[ii], st);
        #pragma unroll
        for (int ii = 0; ii < 4; ii++) {
            l[ii] = l[ii] * corr[ii] + ls[ii];
            *(float4*)&sP[(4 * ty + ii) * 68 + 4 * tx] =
                make_float4(s[ii][0], s[ii][1], s[ii][2], s[ii][3]);
            #pragma unroll
            for (int dd = 0; dd < 4; dd++) o[ii][dd] *= corr[ii];
        }
        __syncthreads();

        #pragma unroll 4
        for (int j = 0; j < 64; j++) {
            float4 v = *(const float4*)&sV[j * 68 + 4 * tx];
            float p0 = sP[(4 * ty + 0) * 68 + j];
            float p1 = sP[(4 * ty + 1) * 68 + j];
            float p2 = sP[(4 * ty + 2) * 68 + j];
            float p3 = sP[(4 * ty + 3) * 68 + j];
            o[0][0] += p0 * v.x; o[0][1] += p0 * v.y; o[0][2] += p0 * v.z; o[0][3] += p0 * v.w;
            o[1][0] += p1 * v.x; o[1][1] += p1 * v.y; o[1][2] += p1 * v.z; o[1][3] += p1 * v.w;
            o[2][0] += p2 * v.x; o[2][1] += p2 * v.y; o[2][2] += p2 * v.z; o[2][3] += p2 * v.w;
            o[3][0] += p3 * v.x; o[3][1] += p3 * v.y; o[3][2] += p3 * v.z; o[3][3] += p3 * v.w;
        }
    }

    #pragma unroll
    for (int ii = 0; ii < 4; ii++) {
        float invl = 1.f / l[ii];
        *(float4*)&g_sa[(size_t)(tbase + 4 * ty + ii) * 512 + h * 64 + 4 * tx] =
            make_float4(o[ii][0] * invl, o[ii][1] * invl, o[ii][2] * invl, o[ii][3] * invl);
    }
}

// ---------------------------------------------------------------------------
// RA flash v2 with extended V = [sv(64) | kr(512)] (d_v = 576).
// Br=64, Bc=32, 512 threads = 16 warps; warp ty owns rows 4ty..4ty+3,
// lane tx owns float4 columns {tx, tx+32, tx+64, tx+96, tx+128(tx<16)}.
// ---------------------------------------------------------------------------
#define RA2_SMEM ((64*68 + 64*33 + 64*33 + 32*576) * 4)

__global__ void __launch_bounds__(512) ra_flash2(const float* __restrict__ wr)
{
    extern __shared__ float sm[];
    float* sQt = sm;                       // [k][i] stride 68
    float* sKt = sQt + 64 * 68;            // [k][j] stride 33
    float* sP  = sKt + 64 * 33;            // [i][j] stride 33
    float* sV  = sP  + 64 * 33;            // [j][d] stride 576

    const int tid = threadIdx.x;
    const int tx  = tid & 31;
    const int ty  = tid >> 5;
    const int b   = blockIdx.y >> 3;
    const int h   = blockIdx.y & 7;
    const int i0  = blockIdx.x * 64;
    const int tbase = b * SEQ + i0;
    const bool lo16 = (tx < 16);

    #pragma unroll
    for (int u = 0; u < 2; u++) {
        int e = tid + (u << 9);
        int rr = e >> 4, d4 = e & 15;
        float4 q = *(const float4*)(g_proj + (size_t)(tbase + rr) * NC + COL_QA + h * 64 + d4 * 4);
        sQt[(d4 * 4 + 0) * 68 + rr] = q.x;
        sQt[(d4 * 4 + 1) * 68 + rr] = q.y;
        sQt[(d4 * 4 + 2) * 68 + rr] = q.z;
        sQt[(d4 * 4 + 3) * 68 + rr] = q.w;
    }

    float mst[4], l[4];
    float acc[4][5][4];
    #pragma unroll
    for (int ii = 0; ii < 4; ii++) {
        mst[ii] = -1e30f; l[ii] = 0.f;
        #pragma unroll
        for (int u = 0; u < 5; u++)
            #pragma unroll
            for (int dd = 0; dd < 4; dd++) acc[ii][u][dd] = 0.f;
    }

    const int nJT = 2 * blockIdx.x + 2;
    for (int jt = 0; jt < nJT; jt++) {
        __syncthreads();
        const int j0 = jt * 32;
        const int jb = b * SEQ + j0;
        {
            int rr = tid >> 4, d4 = tid & 15;
            float4 kv = *(const float4*)(g_proj + (size_t)(jb + rr) * NC + COL_KA + h * 64 + d4 * 4);
            sKt[(d4 * 4 + 0) * 33 + rr] = kv.x;
            sKt[(d4 * 4 + 1) * 33 + rr] = kv.y;
            sKt[(d4 * 4 + 2) * 33 + rr] = kv.z;
            sKt[(d4 * 4 + 3) * 33 + rr] = kv.w;
        }
        for (int e = tid; e < 32 * 144; e += 512) {
            int rr = e / 144;
            int c4 = e - rr * 144;
            float4 v;
            if (c4 < 16)
                v = *(const float4*)(g_sv + (size_t)(jb + rr) * 512 + h * 64 + c4 * 4);
            else
                v = *(const float4*)(g_proj + (size_t)(jb + rr) * NC + COL_KR + c4 * 4 - 64);
            *(float4*)&sV[rr * 576 + c4 * 4] = v;
        }
        __syncthreads();

        // scores: rows 4ty..+3, col tx
        float sc[4] = {0.f, 0.f, 0.f, 0.f};
        #pragma unroll 4
        for (int k = 0; k < 64; k++) {
            float4 q = *(const float4*)&sQt[k * 68 + 4 * ty];
            float kv = sKt[k * 33 + tx];
            sc[0] += q.x * kv; sc[1] += q.y * kv; sc[2] += q.z * kv; sc[3] += q.w * kv;
        }
        const int j_g = j0 + tx;
        float corr[4];
        #pragma unroll
        for (int ii = 0; ii < 4; ii++) {
            int i_g = i0 + 4 * ty + ii;
            sc[ii] = (j_g <= i_g) ? sc[ii] * 0.125f : -1e30f;
        }
        float rm[4];
        #pragma unroll
        for (int ii = 0; ii < 4; ii++) rm[ii] = sc[ii];
        #pragma unroll
        for (int st = 16; st >= 1; st >>= 1)
            #pragma unroll
            for (int ii = 0; ii < 4; ii++)
                rm[ii] = fmaxf(rm[ii], __shfl_xor_sync(0xffffffffu, rm[ii], st));
        float ls[4];
        #pragma unroll
        for (int ii = 0; ii < 4; ii++) {
            float nm = fmaxf(mst[ii], rm[ii]);
            corr[ii] = __expf(mst[ii] - nm);
            mst[ii] = nm;
            float p = __expf(sc[ii] - nm);
            sc[ii] = p;
            ls[ii] = p;
        }
        #pragma unroll
        for (int st = 16; st >= 1; st >>= 1)
            #pragma unroll
            for (int ii = 0; ii < 4; ii++)
                ls[ii] += __shfl_xor_sync(0xffffffffu, ls[ii], st);
        #pragma unroll
        for (int ii = 0; ii < 4; ii++) {
            l[ii] = l[ii] * corr[ii] + ls[ii];
            sP[(4 * ty + ii) * 33 + tx] = sc[ii];
            #pragma unroll
            for (int u = 0; u < 5; u++)
                #pragma unroll
                for (int dd = 0; dd < 4; dd++) acc[ii][u][dd] *= corr[ii];
        }
        __syncthreads();

        #pragma unroll 2
        for (int j = 0; j < 32; j++) {
            float p0 = sP[(4 * ty + 0) * 33 + j];
            float p1 = sP[(4 * ty + 1) * 33 + j];
            float p2 = sP[(4 * ty + 2) * 33 + j];
            float p3 = sP[(4 * ty + 3) * 33 + j];
            const float* vrow = sV + j * 576;
            float4 v0 = *(const float4*)(vrow + 4 * tx);
            float4 v1 = *(const float4*)(vrow + 4 * (tx + 32));
            float4 v2 = *(const float4*)(vrow + 4 * (tx + 64));
            float4 v3 = *(const float4*)(vrow + 4 * (tx + 96));
            float4 v4 = make_float4(0.f, 0.f, 0.f, 0.f);
            if (lo16) v4 = *(const float4*)(vrow + 4 * (tx + 128));
            #define RA_FMA(u, V) \
                acc[0][u][0] += p0 * V.x; acc[0][u][1] += p0 * V.y; acc[0][u][2] += p0 * V.z; acc[0][u][3] += p0 * V.w; \
                acc[1][u][0] += p1 * V.x; acc[1][u][1] += p1 * V.y; acc[1][u][2] += p1 * V.z; acc[1][u][3] += p1 * V.w; \
                acc[2][u][0] += p2 * V.x; acc[2][u][1] += p2 * V.y; acc[2][u][2] += p2 * V.z; acc[2][u][3] += p2 * V.w; \
                acc[3][u][0] += p3 * V.x; acc[3][u][1] += p3 * V.y; acc[3][u][2] += p3 * V.z; acc[3][u][3] += p3 * V.w;
            RA_FMA(0, v0)
            RA_FMA(1, v1)
            RA_FMA(2, v2)
            RA_FMA(3, v3)
            RA_FMA(4, v4)
            #undef RA_FMA
        }
    }

    float invl[4];
    #pragma unroll
    for (int ii = 0; ii < 4; ii++) invl[ii] = 1.f / l[ii];

    // partial rel sums: part[ii][r] = sum over owned kr cols of qr * acc
    float part[4][8];
    #pragma unroll
    for (int ii = 0; ii < 4; ii++)
        #pragma unroll
        for (int r = 0; r < 8; r++) part[ii][r] = 0.f;

    if (!lo16) {
        #pragma unroll
        for (int u = 0; u < 4; u++) {
            const int kb = 4 * (tx + 32 * u) - 64;
            const int r = 2 * u;
            #pragma unroll
            for (int ii = 0; ii < 4; ii++) {
                float4 q = *(const float4*)(g_proj + (size_t)(tbase + 4 * ty + ii) * NC + COL_QR + kb);
                part[ii][r] += q.x * acc[ii][u][0] + q.y * acc[ii][u][1]
                             + q.z * acc[ii][u][2] + q.w * acc[ii][u][3];
            }
        }
    } else {
        #pragma unroll
        for (int u = 1; u < 5; u++) {
            const int kb = 4 * (tx + 32 * u) - 64;
            const int r = 2 * u - 1;
            #pragma unroll
            for (int ii = 0; ii < 4; ii++) {
                float4 q = *(const float4*)(g_proj + (size_t)(tbase + 4 * ty + ii) * NC + COL_QR + kb);
                part[ii][r] += q.x * acc[ii][u][0] + q.y * acc[ii][u][1]
                             + q.z * acc[ii][u][2] + q.w * acc[ii][u][3];
            }
        }
    }
    #pragma unroll
    for (int st = 16; st >= 1; st >>= 1)
        #pragma unroll
        for (int ii = 0; ii < 4; ii++)
            #pragma unroll
            for (int r = 0; r < 8; r++)
                part[ii][r] += __shfl_xor_sync(0xffffffffu, part[ii][r], st);
    #pragma unroll
    for (int ii = 0; ii < 4; ii++)
        #pragma unroll
        for (int r = 0; r < 8; r++)
            part[ii][r] *= invl[ii] * 0.125f;

    if (lo16) {
        float4 wa[4], wb[4];
        #pragma unroll
        for (int dd = 0; dd < 4; dd++) {
            wa[dd] = *(const float4*)(wr + h * 512 + (4 * tx + dd) * 8);
            wb[dd] = *(const float4*)(wr + h * 512 + (4 * tx + dd) * 8 + 4);
        }
        #pragma unroll
        for (int ii = 0; ii < 4; ii++) {
            float outv[4];
            #pragma unroll
            for (int dd = 0; dd < 4; dd++) {
                float ro = part[ii][0] * wa[dd].x + part[ii][1] * wa[dd].y
                         + part[ii][2] * wa[dd].z + part[ii][3] * wa[dd].w
                         + part[ii][4] * wb[dd].x + part[ii][5] * wb[dd].y
                         + part[ii][6] * wb[dd].z + part[ii][7] * wb[dd].w;
                outv[dd] = acc[ii][0][dd] * invl[ii] + ro;
            }
            *(float4*)&g_ra[(size_t)(tbase + 4 * ty + ii) * 512 + h * 64 + 4 * tx] =
                make_float4(outv[0], outv[1], outv[2], outv[3]);
        }
    }
}

// ---------------------------------------------------------------------------
extern "C" void kernel_launch(void* const* d_in, const int* in_sizes, int n_in,
                              void* d_out, int out_size)
{
    (void)in_sizes; (void)n_in; (void)out_size;
    const float* x      = (const float*)d_in[0];
    const float* symb   = (const float*)d_in[1];
    const float* fc     = (const float*)d_in[2];
    const float* fs     = (const float*)d_in[3];
    const float* wq_sa  = (const float*)d_in[4];
    const float* wk_sa  = (const float*)d_in[5];
    const float* wv_sa  = (const float*)d_in[6];
    const float* wo_sa  = (const float*)d_in[7];
    const float* wq_at  = (const float*)d_in[8];
    const float* wk_at  = (const float*)d_in[9];
    const float* wq_rel = (const float*)d_in[10];
    const float* wk_rel = (const float*)d_in[11];
    const float* wr     = (const float*)d_in[12];
    const float* wv_ra  = (const float*)d_in[13];
    const float* wo_ra  = (const float*)d_in[14];
    float* out = (float*)d_out;

    float *proj, *svb, *sab, *rab;
    cudaGetSymbolAddress((void**)&proj, g_proj);
    cudaGetSymbolAddress((void**)&svb,  g_sv);
    cudaGetSymbolAddress((void**)&sab,  g_sa);
    cudaGetSymbolAddress((void**)&rab,  g_ra);

    cudaFuncSetAttribute(sa_flash2, cudaFuncAttributeMaxDynamicSharedMemorySize, SA2_SMEM);
    cudaFuncSetAttribute(ra_flash2, cudaFuncAttributeMaxDynamicSharedMemorySize, RA2_SMEM);

    // 1) fused projections of x: [q_sa|k_sa|v_sa|qa|ka|qr|kr]
    W8 w7;
    w7.p[0] = wq_sa; w7.p[1] = wk_sa; w7.p[2] = wv_sa;
    w7.p[3] = wq_at; w7.p[4] = wk_at; w7.p[5] = wq_rel; w7.p[6] = wk_rel;
    gemm_tf32<<<dim3(NC / 128, NTOK / 128), 256>>>(x, w7, proj, DM, NC, 0);

    // 2) sv = symbols @ wv_ra^T
    W8 wv; for (int i = 0; i < 7; i++) wv.p[i] = wv_ra;
    gemm_tf32<<<dim3(4, NTOK / 128), 256>>>(symb, wv, svb, DM, 512, 0);

    // 3) RoPE on q_sa,k_sa,qa,ka
    rope_kernel<<<(NTOK * 1024) / 256, 256>>>(fc, fs);

    // 4) SA flash
    sa_flash2<<<dim3(SEQ / 64, BATCH * 8), 256, SA2_SMEM>>>();

    // 5) RA flash (fused rel epilogue)
    ra_flash2<<<dim3(SEQ / 64, BATCH * 8), 512, RA2_SMEM>>>(wr);

    // 6) output projections into concatenated out
    W8 wo1; for (int i = 0; i < 7; i++) wo1.p[i] = wo_sa;
    gemm_tf32<<<dim3(4, NTOK / 128), 256>>>(sab, wo1, out, 512, 1024, 0);
    W8 wo2; for (int i = 0; i < 7; i++) wo2.p[i] = wo_ra;
    gemm_tf32<<<dim3(4, NTOK / 128), 256>>>(rab, wo2, out, 512, 1024, 512);
}

// round 6
// speedup vs baseline: 5.0318x; 2.2059x over previous
#include <cuda_runtime.h>
#include <cstdint>

#define BATCH 2
#define SEQ   2048
#define NTOK  (BATCH * SEQ)
#define DM    1024
#define NC    3584

#define COL_QSA 0
#define COL_KSA 512
#define COL_VSA 1024
#define COL_QA  1536
#define COL_KA  2048
#define COL_QR  2560
#define COL_KR  3072

// Scratch (allocation-free rule: __device__ globals)
__device__ float g_proj [NTOK * NC];          // 7 fused projections of x
__device__ float g_sv   [NTOK * 512];         // symbols @ wv_ra^T
__device__ float g_sa   [NTOK * 512];         // SA context
__device__ float g_ra   [NTOK * 512];         // RA context
__device__ float g_attkr[16 * SEQ * 512];     // normalized alpha @ kr per (b,h)

struct W8 { const float* p[7]; };

// ---------------------------------------------------------------------------
// tf32 helpers
// ---------------------------------------------------------------------------
__device__ __forceinline__ float to_tf32(float x) {
    uint32_t u;
    asm("cvt.rna.tf32.f32 %0, %1;" : "=r"(u) : "f"(x));
    return __uint_as_float(u);
}
__device__ __forceinline__ float4 f4_tf32(float4 v) {
    return make_float4(to_tf32(v.x), to_tf32(v.y), to_tf32(v.z), to_tf32(v.w));
}
__device__ __forceinline__ void mma_tf32(float* d, const float* a, const float* b) {
    asm volatile(
        "mma.sync.aligned.m16n8k8.row.col.f32.tf32.tf32.f32 "
        "{%0,%1,%2,%3}, {%4,%5,%6,%7}, {%8,%9}, {%0,%1,%2,%3};"
        : "+f"(d[0]), "+f"(d[1]), "+f"(d[2]), "+f"(d[3])
        : "r"(__float_as_uint(a[0])), "r"(__float_as_uint(a[1])),
          "r"(__float_as_uint(a[2])), "r"(__float_as_uint(a[3])),
          "r"(__float_as_uint(b[0])), "r"(__float_as_uint(b[1])));
}

// ---------------------------------------------------------------------------
// tf32 tensor-core GEMM (unchanged, proven):  C[M,N] = A[M,K] @ W^T
// ---------------------------------------------------------------------------
__global__ void __launch_bounds__(256) gemm_tf32(
    const float* __restrict__ A, W8 w, float* __restrict__ C,
    int K, int ldC, int cOff)
{
    __shared__ float As[128][36];
    __shared__ float Bs[128][36];

    const int tid   = threadIdx.x;
    const int lane  = tid & 31;
    const int wid   = tid >> 5;
    const int warpM = wid >> 2;
    const int warpN = wid & 3;
    const int g     = lane >> 2;
    const int tig   = lane & 3;

    const int mBase = blockIdx.y * 128;
    const int nBase = blockIdx.x * 128;
    const float* Wm = w.p[nBase >> 9];
    const int wrow  = nBase & 511;

    const float* Aptr = A  + (size_t)mBase * K;
    const float* Bptr = Wm + (size_t)wrow  * K;

    float acc[4][4][4];
    #pragma unroll
    for (int mi = 0; mi < 4; mi++)
        #pragma unroll
        for (int ni = 0; ni < 4; ni++)
            #pragma unroll
            for (int c = 0; c < 4; c++) acc[mi][ni][c] = 0.f;

    const int nT = K >> 5;
    float4 pa[4], pb[4];
    #pragma unroll
    for (int u = 0; u < 4; u++) {
        int s_ = tid + (u << 8);
        int r = s_ >> 3, q = s_ & 7;
        pa[u] = *(const float4*)(Aptr + (size_t)r * K + q * 4);
        pb[u] = *(const float4*)(Bptr + (size_t)r * K + q * 4);
    }

    for (int t = 0; t < nT; t++) {
        #pragma unroll
        for (int u = 0; u < 4; u++) {
            int s_ = tid + (u << 8);
            int r = s_ >> 3, q = s_ & 7;
            *(float4*)&As[r][q * 4] = f4_tf32(pa[u]);
            *(float4*)&Bs[r][q * 4] = f4_tf32(pb[u]);
        }
        __syncthreads();

        if (t + 1 < nT) {
            int k0 = (t + 1) << 5;
            #pragma unroll
            for (int u = 0; u < 4; u++) {
                int s_ = tid + (u << 8);
                int r = s_ >> 3, q = s_ & 7;
                pa[u] = *(const float4*)(Aptr + (size_t)r * K + k0 + q * 4);
                pb[u] = *(const float4*)(Bptr + (size_t)r * K + k0 + q * 4);
            }
        }

        #pragma unroll
        for (int ks = 0; ks < 4; ks++) {
            float a[4][4], b[4][2];
            const int kc = ks * 8 + tig;
            #pragma unroll
            for (int mi = 0; mi < 4; mi++) {
                int r0 = warpM * 64 + mi * 16 + g;
                a[mi][0] = As[r0][kc];
                a[mi][1] = As[r0 + 8][kc];
                a[mi][2] = As[r0][kc + 4];
                a[mi][3] = As[r0 + 8][kc + 4];
            }
            #pragma unroll
            for (int ni = 0; ni < 4; ni++) {
                int c0 = warpN * 32 + ni * 8 + g;
                b[ni][0] = Bs[c0][kc];
                b[ni][1] = Bs[c0][kc + 4];
            }
            #pragma unroll
            for (int mi = 0; mi < 4; mi++)
                #pragma unroll
                for (int ni = 0; ni < 4; ni++)
                    mma_tf32(acc[mi][ni], a[mi], b[ni]);
        }
        __syncthreads();
    }

    #pragma unroll
    for (int mi = 0; mi < 4; mi++) {
        int row = mBase + warpM * 64 + mi * 16 + g;
        #pragma unroll
        for (int ni = 0; ni < 4; ni++) {
            int col = cOff + nBase + warpN * 32 + ni * 8 + tig * 2;
            *(float2*)&C[(size_t)row * ldC + col] =
                make_float2(acc[mi][ni][0], acc[mi][ni][1]);
            *(float2*)&C[(size_t)(row + 8) * ldC + col] =
                make_float2(acc[mi][ni][2], acc[mi][ni][3]);
        }
    }
}

// ---------------------------------------------------------------------------
// RoPE in-place (unchanged)
// ---------------------------------------------------------------------------
__global__ void rope_kernel(const float* __restrict__ fc, const float* __restrict__ fs)
{
    int idx = blockIdx.x * blockDim.x + threadIdx.x;
    int token  = idx >> 10;
    int p      = idx & 1023;
    int range  = p >> 9;
    int within = p & 511;
    int col0   = (range ? 1536 : 0) + within * 2;
    int t      = within & 31;
    int s_idx  = token & (SEQ - 1);

    float c  = fc[s_idx * 32 + t];
    float sn = fs[s_idx * 32 + t];
    float* ptr = g_proj + (size_t)token * NC + col0;
    float x0 = ptr[0], x1 = ptr[1];
    ptr[0] = x0 * c - x1 * sn;
    ptr[1] = x0 * sn + x1 * c;
}

// ---------------------------------------------------------------------------
// SA flash v3 (tensor core). Br=64, Bc=64, 256 threads / 8 warps.
// S by warps 0..3 (each m16 x n64). PV: warp (wm=wid&3, wn=wid>>2), N=32/warp.
// ---------------------------------------------------------------------------
#define SA3_SMEM ((64*68*3 + 64*72 + 128) * 4)

__global__ void __launch_bounds__(256) sa_flash3()
{
    extern __shared__ float sm[];
    float* sQ    = sm;              // [64][68] tf32
    float* sK    = sQ + 64*68;      // [64][68] tf32
    float* sP    = sK + 64*68;      // [64][68] tf32
    float* sV    = sP + 64*68;      // [64][72] tf32  (stride 72 => 8 mod 32)
    float* sCorr = sV + 64*72;      // [64]
    float* sL    = sCorr + 64;      // [64]

    const int tid  = threadIdx.x;
    const int lane = tid & 31, wid = tid >> 5;
    const int g    = lane >> 2, tig = lane & 3;
    const int wm   = wid & 3, wn = wid >> 2;
    const int b    = blockIdx.y >> 3, h = blockIdx.y & 7;
    const int bx   = gridDim.x - 1 - blockIdx.x;     // heavy blocks first
    const int i0   = bx * 64;
    const int tbase = b * SEQ + i0;

    #pragma unroll
    for (int u = 0; u < 4; u++) {
        int e = tid + (u << 8);
        int rr = e >> 4, d4 = e & 15;
        *(float4*)&sQ[rr*68 + d4*4] =
            f4_tf32(*(const float4*)(g_proj + (size_t)(tbase+rr)*NC + COL_QSA + h*64 + d4*4));
    }

    float mA = -1e30f, mB = -1e30f, lA = 0.f, lB = 0.f;   // S-warp state
    float o[4][4];
    #pragma unroll
    for (int nt = 0; nt < 4; nt++)
        #pragma unroll
        for (int c = 0; c < 4; c++) o[nt][c] = 0.f;

    const int nJT = bx + 1;
    for (int jt = 0; jt < nJT; jt++) {
        __syncthreads();
        const int jb = b * SEQ + jt * 64;
        #pragma unroll
        for (int u = 0; u < 4; u++) {
            int e = tid + (u << 8);
            int rr = e >> 4, d4 = e & 15;
            const float* base = g_proj + (size_t)(jb+rr)*NC + h*64;
            *(float4*)&sK[rr*68 + d4*4] = f4_tf32(*(const float4*)(base + COL_KSA + d4*4));
            *(float4*)&sV[rr*72 + d4*4] = f4_tf32(*(const float4*)(base + COL_VSA + d4*4));
        }
        __syncthreads();

        if (wid < 4) {
            float c[8][4];
            #pragma unroll
            for (int nt = 0; nt < 8; nt++)
                #pragma unroll
                for (int q = 0; q < 4; q++) c[nt][q] = 0.f;

            #pragma unroll
            for (int ks = 0; ks < 8; ks++) {
                const int r0 = wid*16 + g, kc = ks*8 + tig;
                float a[4];
                a[0] = sQ[r0*68 + kc];     a[1] = sQ[(r0+8)*68 + kc];
                a[2] = sQ[r0*68 + kc + 4]; a[3] = sQ[(r0+8)*68 + kc + 4];
                #pragma unroll
                for (int nt = 0; nt < 8; nt++) {
                    float bf[2];
                    bf[0] = sK[(nt*8+g)*68 + kc];
                    bf[1] = sK[(nt*8+g)*68 + kc + 4];
                    mma_tf32(c[nt], a, bf);
                }
            }

            const int rowA = i0 + wid*16 + g, rowB = rowA + 8;
            float rmA = -1e30f, rmB = -1e30f;
            #pragma unroll
            for (int nt = 0; nt < 8; nt++) {
                int col = jt*64 + nt*8 + tig*2;
                c[nt][0] = (col     <= rowA) ? c[nt][0]*0.125f : -1e30f;
                c[nt][1] = (col + 1 <= rowA) ? c[nt][1]*0.125f : -1e30f;
                c[nt][2] = (col     <= rowB) ? c[nt][2]*0.125f : -1e30f;
                c[nt][3] = (col + 1 <= rowB) ? c[nt][3]*0.125f : -1e30f;
                rmA = fmaxf(rmA, fmaxf(c[nt][0], c[nt][1]));
                rmB = fmaxf(rmB, fmaxf(c[nt][2], c[nt][3]));
            }
            rmA = fmaxf(rmA, __shfl_xor_sync(0xffffffffu, rmA, 1));
            rmA = fmaxf(rmA, __shfl_xor_sync(0xffffffffu, rmA, 2));
            rmB = fmaxf(rmB, __shfl_xor_sync(0xffffffffu, rmB, 1));
            rmB = fmaxf(rmB, __shfl_xor_sync(0xffffffffu, rmB, 2));
            float nmA = fmaxf(mA, rmA), nmB = fmaxf(mB, rmB);
            float cA = __expf(mA - nmA), cB = __expf(mB - nmB);
            mA = nmA; mB = nmB;
            float sAcc = 0.f, sBcc = 0.f;
            const int lrA = wid*16 + g, lrB = lrA + 8;
            #pragma unroll
            for (int nt = 0; nt < 8; nt++) {
                float p0 = __expf(c[nt][0] - nmA);
                float p1 = __expf(c[nt][1] - nmA);
                float p2 = __expf(c[nt][2] - nmB);
                float p3 = __expf(c[nt][3] - nmB);
                sAcc += p0 + p1; sBcc += p2 + p3;
                *(float2*)&sP[lrA*68 + nt*8 + tig*2] = make_float2(to_tf32(p0), to_tf32(p1));
                *(float2*)&sP[lrB*68 + nt*8 + tig*2] = make_float2(to_tf32(p2), to_tf32(p3));
            }
            sAcc += __shfl_xor_sync(0xffffffffu, sAcc, 1);
            sAcc += __shfl_xor_sync(0xffffffffu, sAcc, 2);
            sBcc += __shfl_xor_sync(0xffffffffu, sBcc, 1);
            sBcc += __shfl_xor_sync(0xffffffffu, sBcc, 2);
            lA = lA * cA + sAcc;
            lB = lB * cB + sBcc;
            if (tig == 0) { sCorr[lrA] = cA; sCorr[lrB] = cB; }
        }
        __syncthreads();

        {
            float cA = sCorr[wm*16 + g], cB = sCorr[wm*16 + g + 8];
            #pragma unroll
            for (int nt = 0; nt < 4; nt++) {
                o[nt][0] *= cA; o[nt][1] *= cA;
                o[nt][2] *= cB; o[nt][3] *= cB;
            }
        }
        #pragma unroll
        for (int ks = 0; ks < 8; ks++) {
            const int r0 = wm*16 + g, kc = ks*8 + tig;
            float a[4];
            a[0] = sP[r0*68 + kc];     a[1] = sP[(r0+8)*68 + kc];
            a[2] = sP[r0*68 + kc + 4]; a[3] = sP[(r0+8)*68 + kc + 4];
            #pragma unroll
            for (int nt = 0; nt < 4; nt++) {
                const int n_ = wn*32 + nt*8 + g;
                float bf[2];
                bf[0] = sV[kc*72 + n_];
                bf[1] = sV[(kc+4)*72 + n_];
                mma_tf32(o[nt], a, bf);
            }
        }
    }

    if (wid < 4 && tig == 0) {
        sL[wid*16 + g] = lA;
        sL[wid*16 + g + 8] = lB;
    }
    __syncthreads();
    {
        const float invA = 1.f / sL[wm*16 + g];
        const float invB = 1.f / sL[wm*16 + g + 8];
        const int rowA = wm*16 + g;
        #pragma unroll
        for (int nt = 0; nt < 4; nt++) {
            int col = wn*32 + nt*8 + tig*2;
            *(float2*)&g_sa[(size_t)(tbase+rowA)*512 + h*64 + col] =
                make_float2(o[nt][0]*invA, o[nt][1]*invA);
            *(float2*)&g_sa[(size_t)(tbase+rowA+8)*512 + h*64 + col] =
                make_float2(o[nt][2]*invB, o[nt][3]*invB);
        }
    }
}

// ---------------------------------------------------------------------------
// RA flash v3 (tensor core), extended V = [sv(64) | kr(512)], d_v = 576.
// Br=64, Bc=64, 512 threads / 16 warps. S by warps 0..3 (m16 x n64 each).
// PV warp grid 4M x 4N (N=144/warp -> 18 n-tiles, 72 accum regs).
// Writes g_ra cols<64 and normalized attkr to g_attkr.
// ---------------------------------------------------------------------------
#define RA3_SMEM ((64*68*3 + 64*584 + 128) * 4)

__global__ void __launch_bounds__(512) ra_flash3()
{
    extern __shared__ float sm[];
    float* sQ    = sm;              // [64][68]
    float* sK    = sQ + 64*68;      // [64][68]
    float* sP    = sK + 64*68;      // [64][68]
    float* sV    = sP + 64*68;      // [64][584]  (stride 584 => 8 mod 32)
    float* sCorr = sV + 64*584;     // [64]
    float* sL    = sCorr + 64;      // [64]

    const int tid  = threadIdx.x;
    const int lane = tid & 31, wid = tid >> 5;
    const int g    = lane >> 2, tig = lane & 3;
    const int wm   = wid & 3, wn = wid >> 2;
    const int b    = blockIdx.y >> 3, h = blockIdx.y & 7;
    const int bx   = gridDim.x - 1 - blockIdx.x;
    const int i0   = bx * 64;
    const int tbase = b * SEQ + i0;

    #pragma unroll
    for (int u = 0; u < 2; u++) {
        int e = tid + (u << 9);
        int rr = e >> 4, d4 = e & 15;
        *(float4*)&sQ[rr*68 + d4*4] =
            f4_tf32(*(const float4*)(g_proj + (size_t)(tbase+rr)*NC + COL_QA + h*64 + d4*4));
    }

    float mA = -1e30f, mB = -1e30f, lA = 0.f, lB = 0.f;
    float o[18][4];
    #pragma unroll
    for (int nt = 0; nt < 18; nt++)
        #pragma unroll
        for (int c = 0; c < 4; c++) o[nt][c] = 0.f;

    const int nJT = bx + 1;
    for (int jt = 0; jt < nJT; jt++) {
        __syncthreads();
        const int jb = b * SEQ + jt * 64;
        #pragma unroll
        for (int u = 0; u < 2; u++) {
            int e = tid + (u << 9);
            int rr = e >> 4, d4 = e & 15;
            *(float4*)&sK[rr*68 + d4*4] =
                f4_tf32(*(const float4*)(g_proj + (size_t)(jb+rr)*NC + COL_KA + h*64 + d4*4));
        }
        for (int e = tid; e < 64 * 146; e += 512) {
            int rr = e / 146, c4 = e - rr * 146;
            float4 v;
            if (c4 < 16)
                v = *(const float4*)(g_sv + (size_t)(jb+rr)*512 + h*64 + c4*4);
            else
                v = *(const float4*)(g_proj + (size_t)(jb+rr)*NC + COL_KR + (c4-16)*4);
            *(float4*)&sV[rr*584 + c4*4] = f4_tf32(v);
        }
        __syncthreads();

        if (wid < 4) {
            float c[8][4];
            #pragma unroll
            for (int nt = 0; nt < 8; nt++)
                #pragma unroll
                for (int q = 0; q < 4; q++) c[nt][q] = 0.f;

            #pragma unroll
            for (int ks = 0; ks < 8; ks++) {
                const int r0 = wid*16 + g, kc = ks*8 + tig;
                float a[4];
                a[0] = sQ[r0*68 + kc];     a[1] = sQ[(r0+8)*68 + kc];
                a[2] = sQ[r0*68 + kc + 4]; a[3] = sQ[(r0+8)*68 + kc + 4];
                #pragma unroll
                for (int nt = 0; nt < 8; nt++) {
                    float bf[2];
                    bf[0] = sK[(nt*8+g)*68 + kc];
                    bf[1] = sK[(nt*8+g)*68 + kc + 4];
                    mma_tf32(c[nt], a, bf);
                }
            }

            const int rowA = i0 + wid*16 + g, rowB = rowA + 8;
            float rmA = -1e30f, rmB = -1e30f;
            #pragma unroll
            for (int nt = 0; nt < 8; nt++) {
                int col = jt*64 + nt*8 + tig*2;
                c[nt][0] = (col     <= rowA) ? c[nt][0]*0.125f : -1e30f;
                c[nt][1] = (col + 1 <= rowA) ? c[nt][1]*0.125f : -1e30f;
                c[nt][2] = (col     <= rowB) ? c[nt][2]*0.125f : -1e30f;
                c[nt][3] = (col + 1 <= rowB) ? c[nt][3]*0.125f : -1e30f;
                rmA = fmaxf(rmA, fmaxf(c[nt][0], c[nt][1]));
                rmB = fmaxf(rmB, fmaxf(c[nt][2], c[nt][3]));
            }
            rmA = fmaxf(rmA, __shfl_xor_sync(0xffffffffu, rmA, 1));
            rmA = fmaxf(rmA, __shfl_xor_sync(0xffffffffu, rmA, 2));
            rmB = fmaxf(rmB, __shfl_xor_sync(0xffffffffu, rmB, 1));
            rmB = fmaxf(rmB, __shfl_xor_sync(0xffffffffu, rmB, 2));
            float nmA = fmaxf(mA, rmA), nmB = fmaxf(mB, rmB);
            float cA = __expf(mA - nmA), cB = __expf(mB - nmB);
            mA = nmA; mB = nmB;
            float sAcc = 0.f, sBcc = 0.f;
            const int lrA = wid*16 + g, lrB = lrA + 8;
            #pragma unroll
            for (int nt = 0; nt < 8; nt++) {
                float p0 = __expf(c[nt][0] - nmA);
                float p1 = __expf(c[nt][1] - nmA);
                float p2 = __expf(c[nt][2] - nmB);
                float p3 = __expf(c[nt][3] - nmB);
                sAcc += p0 + p1; sBcc += p2 + p3;
                *(float2*)&sP[lrA*68 + nt*8 + tig*2] = make_float2(to_tf32(p0), to_tf32(p1));
                *(float2*)&sP[lrB*68 + nt*8 + tig*2] = make_float2(to_tf32(p2), to_tf32(p3));
            }
            sAcc += __shfl_xor_sync(0xffffffffu, sAcc, 1);
            sAcc += __shfl_xor_sync(0xffffffffu, sAcc, 2);
            sBcc += __shfl_xor_sync(0xffffffffu, sBcc, 1);
            sBcc += __shfl_xor_sync(0xffffffffu, sBcc, 2);
            lA = lA * cA + sAcc;
            lB = lB * cB + sBcc;
            if (tig == 0) { sCorr[lrA] = cA; sCorr[lrB] = cB; }
        }
        __syncthreads();

        {
            float cA = sCorr[wm*16 + g], cB = sCorr[wm*16 + g + 8];
            #pragma unroll
            for (int nt = 0; nt < 18; nt++) {
                o[nt][0] *= cA; o[nt][1] *= cA;
                o[nt][2] *= cB; o[nt][3] *= cB;
            }
        }
        #pragma unroll
        for (int ks = 0; ks < 8; ks++) {
            const int r0 = wm*16 + g, kc = ks*8 + tig;
            float a[4];
            a[0] = sP[r0*68 + kc];     a[1] = sP[(r0+8)*68 + kc];
            a[2] = sP[r0*68 + kc + 4]; a[3] = sP[(r0+8)*68 + kc + 4];
            #pragma unroll
            for (int nt = 0; nt < 18; nt++) {
                const int n_ = wn*144 + nt*8 + g;
                float bf[2];
                bf[0] = sV[kc*584 + n_];
                bf[1] = sV[(kc+4)*584 + n_];
                mma_tf32(o[nt], a, bf);
            }
        }
    }

    if (wid < 4 && tig == 0) {
        sL[wid*16 + g] = lA;
        sL[wid*16 + g + 8] = lB;
    }
    __syncthreads();
    {
        const float invA = 1.f / sL[wm*16 + g];
        const float invB = 1.f / sL[wm*16 + g + 8];
        const int rowA = wm*16 + g;
        const size_t akBase = ((size_t)blockIdx.y * SEQ + i0);
        #pragma unroll
        for (int nt = 0; nt < 18; nt++) {
            int col = wn*144 + nt*8 + tig*2;
            float2 vA = make_float2(o[nt][0]*invA, o[nt][1]*invA);
            float2 vB = make_float2(o[nt][2]*invB, o[nt][3]*invB);
            if (col < 64) {
                *(float2*)&g_ra[(size_t)(tbase+rowA)*512 + h*64 + col] = vA;
                *(float2*)&g_ra[(size_t)(tbase+rowA+8)*512 + h*64 + col] = vB;
            } else {
                *(float2*)&g_attkr[(akBase + rowA)*512 + col - 64] = vA;
                *(float2*)&g_attkr[(akBase + rowA + 8)*512 + col - 64] = vB;
            }
        }
    }
}

// ---------------------------------------------------------------------------
// ra_post: attrel[r] = rel_scale * qr[i,r,:].(alpha@kr)[i,r,:]; add rel_out
// via wr into g_ra. One warp per (token, h).
// ---------------------------------------------------------------------------
__global__ void __launch_bounds__(256) ra_post(const float* __restrict__ wr)
{
    const int lane = threadIdx.x & 31;
    const int wid  = threadIdx.x >> 5;
    const int job  = blockIdx.x * 8 + wid;          // NTOK*8 jobs
    const int h     = job & 7;
    const int token = job >> 3;
    const int bb    = token >> 11;                  // SEQ = 2048
    const int ii    = token & (SEQ - 1);

    const int r = lane >> 2, q = lane & 3;          // lane covers d = r*64 + q*16 .. +15
    const float* qr = g_proj + (size_t)token * NC + COL_QR;
    const float* ak = g_attkr + (((size_t)(bb*8 + h)) * SEQ + ii) * 512;

    float part = 0.f;
    #pragma unroll
    for (int u = 0; u < 4; u++) {
        float4 qv = *(const float4*)(qr + r*64 + q*16 + u*4);
        float4 av = *(const float4*)(ak + r*64 + q*16 + u*4);
        part += qv.x*av.x + qv.y*av.y + qv.z*av.z + qv.w*av.w;
    }
    part += __shfl_xor_sync(0xffffffffu, part, 1);
    part += __shfl_xor_sync(0xffffffffu, part, 2);
    part *= 0.125f;                                  // rel_scale

    float pr[8];
    #pragma unroll
    for (int r2 = 0; r2 < 8; r2++)
        pr[r2] = __shfl_sync(0xffffffffu, part, r2 << 2);

    const float* wrh = wr + h * 512;
    float* dst = g_ra + (size_t)token * 512 + h * 64;
    #pragma unroll
    for (int dd = 0; dd < 2; dd++) {
        int d = lane * 2 + dd;
        float ro = 0.f;
        #pragma unroll
        for (int r2 = 0; r2 < 8; r2++)
            ro += pr[r2] * wrh[d*8 + r2];
        dst[d] += ro;
    }
}

// ---------------------------------------------------------------------------
extern "C" void kernel_launch(void* const* d_in, const int* in_sizes, int n_in,
                              void* d_out, int out_size)
{
    (void)in_sizes; (void)n_in; (void)out_size;
    const float* x      = (const float*)d_in[0];
    const float* symb   = (const float*)d_in[1];
    const float* fc     = (const float*)d_in[2];
    const float* fs     = (const float*)d_in[3];
    const float* wq_sa  = (const float*)d_in[4];
    const float* wk_sa  = (const float*)d_in[5];
    const float* wv_sa  = (const float*)d_in[6];
    const float* wo_sa  = (const float*)d_in[7];
    const float* wq_at  = (const float*)d_in[8];
    const float* wk_at  = (const float*)d_in[9];
    const float* wq_rel = (const float*)d_in[10];
    const float* wk_rel = (const float*)d_in[11];
    const float* wr     = (const float*)d_in[12];
    const float* wv_ra  = (const float*)d_in[13];
    const float* wo_ra  = (const float*)d_in[14];
    float* out = (float*)d_out;

    float *proj, *svb, *sab, *rab;
    cudaGetSymbolAddress((void**)&proj, g_proj);
    cudaGetSymbolAddress((void**)&svb,  g_sv);
    cudaGetSymbolAddress((void**)&sab,  g_sa);
    cudaGetSymbolAddress((void**)&rab,  g_ra);

    cudaFuncSetAttribute(sa_flash3, cudaFuncAttributeMaxDynamicSharedMemorySize, SA3_SMEM);
    cudaFuncSetAttribute(ra_flash3, cudaFuncAttributeMaxDynamicSharedMemorySize, RA3_SMEM);

    // 1) fused projections of x
    W8 w7;
    w7.p[0] = wq_sa; w7.p[1] = wk_sa; w7.p[2] = wv_sa;
    w7.p[3] = wq_at; w7.p[4] = wk_at; w7.p[5] = wq_rel; w7.p[6] = wk_rel;
    gemm_tf32<<<dim3(NC / 128, NTOK / 128), 256>>>(x, w7, proj, DM, NC, 0);

    // 2) sv = symbols @ wv_ra^T
    W8 wv; for (int i = 0; i < 7; i++) wv.p[i] = wv_ra;
    gemm_tf32<<<dim3(4, NTOK / 128), 256>>>(symb, wv, svb, DM, 512, 0);

    // 3) RoPE
    rope_kernel<<<(NTOK * 1024) / 256, 256>>>(fc, fs);

    // 4) SA flash (tensor core)
    sa_flash3<<<dim3(SEQ / 64, BATCH * 8), 256, SA3_SMEM>>>();

    // 5) RA flash (tensor core) + rel post pass
    ra_flash3<<<dim3(SEQ / 64, BATCH * 8), 512, RA3_SMEM>>>();
    ra_post<<<NTOK, 256>>>(wr);

    // 6) output projections
    W8 wo1; for (int i = 0; i < 7; i++) wo1.p[i] = wo_sa;
    gemm_tf32<<<dim3(4, NTOK / 128), 256>>>(sab, wo1, out, 512, 1024, 0);
    W8 wo2; for (int i = 0; i < 7; i++) wo2.p[i] = wo_ra;
    gemm_tf32<<<dim3(4, NTOK / 128), 256>>>(rab, wo2, out, 512, 1024, 512);
}

// round 7
// speedup vs baseline: 5.1049x; 1.0145x over previous
#include <cuda_runtime.h>
#include <cstdint>

#define BATCH 2
#define SEQ   2048
#define NTOK  (BATCH * SEQ)
#define DM    1024
#define NC    3584

#define COL_QSA 0
#define COL_KSA 512
#define COL_VSA 1024
#define COL_QA  1536
#define COL_KA  2048
#define COL_QR  2560
#define COL_KR  3072

// Scratch (allocation-free rule: __device__ globals)
__device__ float g_proj [NTOK * NC];          // 7 fused projections of x
__device__ float g_sv   [NTOK * 512];         // symbols @ wv_ra^T
__device__ float g_sa   [NTOK * 512];         // SA context
__device__ float g_ra   [NTOK * 512];         // RA context
__device__ float g_attkr[16 * SEQ * 512];     // normalized alpha @ kr per (b,h)

struct W8 { const float* p[7]; };

// ---------------------------------------------------------------------------
// tf32 / mma / ldmatrix helpers
// ---------------------------------------------------------------------------
__device__ __forceinline__ float to_tf32(float x) {
    uint32_t u;
    asm("cvt.rna.tf32.f32 %0, %1;" : "=r"(u) : "f"(x));
    return __uint_as_float(u);
}
__device__ __forceinline__ float4 f4_tf32(float4 v) {
    return make_float4(to_tf32(v.x), to_tf32(v.y), to_tf32(v.z), to_tf32(v.w));
}
__device__ __forceinline__ void mma_tf32u(float* d, const uint32_t* a, const uint32_t* b) {
    asm volatile(
        "mma.sync.aligned.m16n8k8.row.col.f32.tf32.tf32.f32 "
        "{%0,%1,%2,%3}, {%4,%5,%6,%7}, {%8,%9}, {%0,%1,%2,%3};"
        : "+f"(d[0]), "+f"(d[1]), "+f"(d[2]), "+f"(d[3])
        : "r"(a[0]), "r"(a[1]), "r"(a[2]), "r"(a[3]), "r"(b[0]), "r"(b[1]));
}
__device__ __forceinline__ uint32_t sm_addr(const void* p) {
    return (uint32_t)__cvta_generic_to_shared(p);
}
__device__ __forceinline__ void ldsm4(uint32_t* r, uint32_t a) {
    asm volatile("ldmatrix.sync.aligned.m8n8.x4.shared.b16 {%0,%1,%2,%3}, [%4];"
        : "=r"(r[0]), "=r"(r[1]), "=r"(r[2]), "=r"(r[3]) : "r"(a));
}
__device__ __forceinline__ void ldsm2(uint32_t* r, uint32_t a) {
    asm volatile("ldmatrix.sync.aligned.m8n8.x2.shared.b16 {%0,%1}, [%2];"
        : "=r"(r[0]), "=r"(r[1]) : "r"(a));
}

// ---------------------------------------------------------------------------
// tf32 tensor-core GEMM:  C[M,N] = A[M,K] @ W^T  — ldmatrix fragment loads
// ---------------------------------------------------------------------------
__global__ void __launch_bounds__(256) gemm_tf32(
    const float* __restrict__ A, W8 w, float* __restrict__ C,
    int K, int ldC, int cOff)
{
    __shared__ float As[128][36];
    __shared__ float Bs[128][36];

    const int tid   = threadIdx.x;
    const int lane  = tid & 31;
    const int wid   = tid >> 5;
    const int warpM = wid >> 2;
    const int warpN = wid & 3;
    const int g     = lane >> 2;
    const int tig   = lane & 3;

    const int mBase = blockIdx.y * 128;
    const int nBase = blockIdx.x * 128;
    const float* Wm = w.p[nBase >> 9];
    const int wrow  = nBase & 511;

    const float* Aptr = A  + (size_t)mBase * K;
    const float* Bptr = Wm + (size_t)wrow  * K;

    float acc[4][4][4];
    #pragma unroll
    for (int mi = 0; mi < 4; mi++)
        #pragma unroll
        for (int ni = 0; ni < 4; ni++)
            #pragma unroll
            for (int c = 0; c < 4; c++) acc[mi][ni][c] = 0.f;

    // ldmatrix base addresses
    const int lrow  = (lane & 7) + ((lane >> 3) & 1) * 8;
    const int lcol4 = (lane >> 4) * 4;
    const int bcol4 = ((lane >> 3) & 1) * 4;
    uint32_t aB[4], bB[4];
    #pragma unroll
    for (int mi = 0; mi < 4; mi++)
        aB[mi] = sm_addr(&As[warpM*64 + mi*16 + lrow][lcol4]);
    #pragma unroll
    for (int ni = 0; ni < 4; ni++)
        bB[ni] = sm_addr(&Bs[warpN*32 + ni*8 + (lane & 7)][bcol4]);

    const int nT = K >> 5;
    float4 pa[4], pb[4];
    #pragma unroll
    for (int u = 0; u < 4; u++) {
        int s_ = tid + (u << 8);
        int r = s_ >> 3, q = s_ & 7;
        pa[u] = *(const float4*)(Aptr + (size_t)r * K + q * 4);
        pb[u] = *(const float4*)(Bptr + (size_t)r * K + q * 4);
    }

    for (int t = 0; t < nT; t++) {
        #pragma unroll
        for (int u = 0; u < 4; u++) {
            int s_ = tid + (u << 8);
            int r = s_ >> 3, q = s_ & 7;
            *(float4*)&As[r][q * 4] = f4_tf32(pa[u]);
            *(float4*)&Bs[r][q * 4] = f4_tf32(pb[u]);
        }
        __syncthreads();

        if (t + 1 < nT) {
            int k0 = (t + 1) << 5;
            #pragma unroll
            for (int u = 0; u < 4; u++) {
                int s_ = tid + (u << 8);
                int r = s_ >> 3, q = s_ & 7;
                pa[u] = *(const float4*)(Aptr + (size_t)r * K + k0 + q * 4);
                pb[u] = *(const float4*)(Bptr + (size_t)r * K + k0 + q * 4);
            }
        }

        #pragma unroll
        for (int ks = 0; ks < 4; ks++) {
            uint32_t a4[4][4], b2[4][2];
            #pragma unroll
            for (int mi = 0; mi < 4; mi++) ldsm4(a4[mi], aB[mi] + ks * 32);
            #pragma unroll
            for (int ni = 0; ni < 4; ni++) ldsm2(b2[ni], bB[ni] + ks * 32);
            #pragma unroll
            for (int mi = 0; mi < 4; mi++)
                #pragma unroll
                for (int ni = 0; ni < 4; ni++)
                    mma_tf32u(acc[mi][ni], a4[mi], b2[ni]);
        }
        __syncthreads();
    }

    #pragma unroll
    for (int mi = 0; mi < 4; mi++) {
        int row = mBase + warpM * 64 + mi * 16 + g;
        #pragma unroll
        for (int ni = 0; ni < 4; ni++) {
            int col = cOff + nBase + warpN * 32 + ni * 8 + tig * 2;
            *(float2*)&C[(size_t)row * ldC + col] =
                make_float2(acc[mi][ni][0], acc[mi][ni][1]);
            *(float2*)&C[(size_t)(row + 8) * ldC + col] =
                make_float2(acc[mi][ni][2], acc[mi][ni][3]);
        }
    }
}

// ---------------------------------------------------------------------------
// RoPE in-place (unchanged)
// ---------------------------------------------------------------------------
__global__ void rope_kernel(const float* __restrict__ fc, const float* __restrict__ fs)
{
    int idx = blockIdx.x * blockDim.x + threadIdx.x;
    int token  = idx >> 10;
    int p      = idx & 1023;
    int range  = p >> 9;
    int within = p & 511;
    int col0   = (range ? 1536 : 0) + within * 2;
    int t      = within & 31;
    int s_idx  = token & (SEQ - 1);

    float c  = fc[s_idx * 32 + t];
    float sn = fs[s_idx * 32 + t];
    float* ptr = g_proj + (size_t)token * NC + col0;
    float x0 = ptr[0], x1 = ptr[1];
    ptr[0] = x0 * c - x1 * sn;
    ptr[1] = x0 * sn + x1 * c;
}

// ---------------------------------------------------------------------------
// SA flash v4: Br=Bc=64, 256 thr / 8 warps. S on ALL warps (band=wid&3 rows,
// half=wid>>2 n-half). Softmax row state in smem (sM/sL/sCorr) with 2-way
// partial combine. PV on all warps. ldmatrix for A/S-B fragments.
// ---------------------------------------------------------------------------
#define SA4_SMEM ((64*68*3 + 64*72 + 512) * 4)

__global__ void __launch_bounds__(256) sa_flash4()
{
    extern __shared__ float sm[];
    float* sQ    = sm;               // [64][68] (row i, 16B segs of d)
    float* sK    = sQ + 64*68;       // [64][68] (row j, d)
    float* sP    = sK + 64*68;       // [64][68] (row i, j)
    float* sV    = sP + 64*68;       // [64][72] (row j, d) scalar B loads
    float* sM    = sV + 64*72;       // [64]
    float* sL    = sM + 64;          // [64]
    float* sCorr = sL + 64;          // [64]
    float* sMaxP = sCorr + 64;       // [2][64]
    float* sSumP = sMaxP + 128;      // [2][64]

    const int tid  = threadIdx.x;
    const int lane = tid & 31, wid = tid >> 5;
    const int g    = lane >> 2, tig = lane & 3;
    const int wband = wid & 3, whalf = wid >> 2;
    const int r0   = wband * 16;
    const int b    = blockIdx.y >> 3, h = blockIdx.y & 7;
    const int bx   = gridDim.x - 1 - blockIdx.x;
    const int i0   = bx * 64;
    const int tbase = b * SEQ + i0;

    if (tid < 64) { sM[tid] = -1e30f; sL[tid] = 0.f; }

    #pragma unroll
    for (int u = 0; u < 4; u++) {
        int e = tid + (u << 8);
        int rr = e >> 4, d4 = e & 15;
        *(float4*)&sQ[rr*68 + d4*4] =
            f4_tf32(*(const float4*)(g_proj + (size_t)(tbase+rr)*NC + COL_QSA + h*64 + d4*4));
    }

    // ldmatrix bases
    const int lrow  = (lane & 7) + ((lane >> 3) & 1) * 8;
    const int lcol4 = (lane >> 4) * 4;
    const int bcol4 = ((lane >> 3) & 1) * 4;
    const uint32_t aQb = sm_addr(&sQ[(r0 + lrow)*68 + lcol4]);
    const uint32_t aPb = sm_addr(&sP[(r0 + lrow)*68 + lcol4]);
    uint32_t bKb[4];
    #pragma unroll
    for (int nt = 0; nt < 4; nt++)
        bKb[nt] = sm_addr(&sK[(whalf*32 + nt*8 + (lane & 7))*68 + bcol4]);

    const int rA = r0 + g, rB = rA + 8;

    float o[4][4];
    #pragma unroll
    for (int nt = 0; nt < 4; nt++)
        #pragma unroll
        for (int c = 0; c < 4; c++) o[nt][c] = 0.f;

    const int nJT = bx + 1;
    for (int jt = 0; jt < nJT; jt++) {
        __syncthreads();
        const int jb = b * SEQ + jt * 64;
        #pragma unroll
        for (int u = 0; u < 4; u++) {
            int e = tid + (u << 8);
            int rr = e >> 4, d4 = e & 15;
            const float* base = g_proj + (size_t)(jb+rr)*NC + h*64;
            *(float4*)&sK[rr*68 + d4*4] = f4_tf32(*(const float4*)(base + COL_KSA + d4*4));
            *(float4*)&sV[rr*72 + d4*4] = f4_tf32(*(const float4*)(base + COL_VSA + d4*4));
        }
        __syncthreads();

        // ---- S: each warp m16 x n32 ----
        float c_[4][4];
        #pragma unroll
        for (int nt = 0; nt < 4; nt++)
            #pragma unroll
            for (int q = 0; q < 4; q++) c_[nt][q] = 0.f;
        #pragma unroll
        for (int ks = 0; ks < 8; ks++) {
            uint32_t a4[4];
            ldsm4(a4, aQb + ks * 32);
            #pragma unroll
            for (int nt = 0; nt < 4; nt++) {
                uint32_t b2[2];
                ldsm2(b2, bKb[nt] + ks * 32);
                mma_tf32u(c_[nt], a4, b2);
            }
        }
        const int rowA = i0 + rA, rowB = i0 + rB;
        float rmA = -1e30f, rmB = -1e30f;
        #pragma unroll
        for (int nt = 0; nt < 4; nt++) {
            int col = jt*64 + whalf*32 + nt*8 + tig*2;
            c_[nt][0] = (col     <= rowA) ? c_[nt][0]*0.125f : -1e30f;
            c_[nt][1] = (col + 1 <= rowA) ? c_[nt][1]*0.125f : -1e30f;
            c_[nt][2] = (col     <= rowB) ? c_[nt][2]*0.125f : -1e30f;
            c_[nt][3] = (col + 1 <= rowB) ? c_[nt][3]*0.125f : -1e30f;
            rmA = fmaxf(rmA, fmaxf(c_[nt][0], c_[nt][1]));
            rmB = fmaxf(rmB, fmaxf(c_[nt][2], c_[nt][3]));
        }
        rmA = fmaxf(rmA, __shfl_xor_sync(0xffffffffu, rmA, 1));
        rmA = fmaxf(rmA, __shfl_xor_sync(0xffffffffu, rmA, 2));
        rmB = fmaxf(rmB, __shfl_xor_sync(0xffffffffu, rmB, 1));
        rmB = fmaxf(rmB, __shfl_xor_sync(0xffffffffu, rmB, 2));
        if (tig == 0) { sMaxP[whalf*64 + rA] = rmA; sMaxP[whalf*64 + rB] = rmB; }
        __syncthreads();

        float newmA = fmaxf(sM[rA], fmaxf(sMaxP[rA], sMaxP[64 + rA]));
        float newmB = fmaxf(sM[rB], fmaxf(sMaxP[rB], sMaxP[64 + rB]));
        float corrA = __expf(sM[rA] - newmA);
        float corrB = __expf(sM[rB] - newmB);
        float sAcc = 0.f, sBcc = 0.f;
        #pragma unroll
        for (int nt = 0; nt < 4; nt++) {
            float p0 = __expf(c_[nt][0] - newmA);
            float p1 = __expf(c_[nt][1] - newmA);
            float p2 = __expf(c_[nt][2] - newmB);
            float p3 = __expf(c_[nt][3] - newmB);
            sAcc += p0 + p1; sBcc += p2 + p3;
            *(float2*)&sP[rA*68 + whalf*32 + nt*8 + tig*2] = make_float2(to_tf32(p0), to_tf32(p1));
            *(float2*)&sP[rB*68 + whalf*32 + nt*8 + tig*2] = make_float2(to_tf32(p2), to_tf32(p3));
        }
        sAcc += __shfl_xor_sync(0xffffffffu, sAcc, 1);
        sAcc += __shfl_xor_sync(0xffffffffu, sAcc, 2);
        sBcc += __shfl_xor_sync(0xffffffffu, sBcc, 1);
        sBcc += __shfl_xor_sync(0xffffffffu, sBcc, 2);
        if (tig == 0) { sSumP[whalf*64 + rA] = sAcc; sSumP[whalf*64 + rB] = sBcc; }
        if (whalf == 0 && tig == 0) { sCorr[rA] = corrA; sCorr[rB] = corrB; }
        __syncthreads();

        if (whalf == 0 && tig == 0) {
            sM[rA] = newmA; sL[rA] = sL[rA]*corrA + sSumP[rA] + sSumP[64 + rA];
            sM[rB] = newmB; sL[rB] = sL[rB]*corrB + sSumP[rB] + sSumP[64 + rB];
        }

        // ---- PV: each warp m16 x n32 ----
        {
            float cA = sCorr[rA], cB = sCorr[rB];
            #pragma unroll
            for (int nt = 0; nt < 4; nt++) {
                o[nt][0] *= cA; o[nt][1] *= cA;
                o[nt][2] *= cB; o[nt][3] *= cB;
            }
        }
        #pragma unroll
        for (int ks = 0; ks < 8; ks++) {
            uint32_t a4[4];
            ldsm4(a4, aPb + ks * 32);
            const int kc = ks*8 + tig;
            #pragma unroll
            for (int nt = 0; nt < 4; nt++) {
                const int n_ = whalf*32 + nt*8 + g;
                uint32_t b2[2];
                b2[0] = __float_as_uint(sV[kc*72 + n_]);
                b2[1] = __float_as_uint(sV[(kc+4)*72 + n_]);
                mma_tf32u(o[nt], a4, b2);
            }
        }
    }

    __syncthreads();
    {
        const float invA = 1.f / sL[rA];
        const float invB = 1.f / sL[rB];
        #pragma unroll
        for (int nt = 0; nt < 4; nt++) {
            int col = whalf*32 + nt*8 + tig*2;
            *(float2*)&g_sa[(size_t)(tbase+rA)*512 + h*64 + col] =
                make_float2(o[nt][0]*invA, o[nt][1]*invA);
            *(float2*)&g_sa[(size_t)(tbase+rB)*512 + h*64 + col] =
                make_float2(o[nt][2]*invB, o[nt][3]*invB);
        }
    }
}

// ---------------------------------------------------------------------------
// RA flash v4: extended V = [sv(64) | kr(512)], d_v=576. Br=Bc=64, 512 thr /
// 16 warps. S on ALL warps (band=wid&3 rows, quarter=wid>>2 n-quarter, 4-way
// partial combine). PV 4x4 warp grid (144 d-cols per warp). ldmatrix frags.
// ---------------------------------------------------------------------------
#define RA4_SMEM ((64*68*3 + 64*584 + 704) * 4)

__global__ void __launch_bounds__(512) ra_flash4()
{
    extern __shared__ float sm[];
    float* sQ    = sm;               // [64][68]
    float* sK    = sQ + 64*68;       // [64][68]
    float* sP    = sK + 64*68;       // [64][68]
    float* sV    = sP + 64*68;       // [64][584]
    float* sM    = sV + 64*584;      // [64]
    float* sL    = sM + 64;          // [64]
    float* sCorr = sL + 64;          // [64]
    float* sMaxP = sCorr + 64;       // [4][64]
    float* sSumP = sMaxP + 256;      // [4][64]

    const int tid  = threadIdx.x;
    const int lane = tid & 31, wid = tid >> 5;
    const int g    = lane >> 2, tig = lane & 3;
    const int wband = wid & 3, wq = wid >> 2;
    const int r0   = wband * 16;
    const int b    = blockIdx.y >> 3, h = blockIdx.y & 7;
    const int bx   = gridDim.x - 1 - blockIdx.x;
    const int i0   = bx * 64;
    const int tbase = b * SEQ + i0;

    if (tid < 64) { sM[tid] = -1e30f; sL[tid] = 0.f; }

    #pragma unroll
    for (int u = 0; u < 2; u++) {
        int e = tid + (u << 9);
        int rr = e >> 4, d4 = e & 15;
        *(float4*)&sQ[rr*68 + d4*4] =
            f4_tf32(*(const float4*)(g_proj + (size_t)(tbase+rr)*NC + COL_QA + h*64 + d4*4));
    }

    const int lrow  = (lane & 7) + ((lane >> 3) & 1) * 8;
    const int lcol4 = (lane >> 4) * 4;
    const int bcol4 = ((lane >> 3) & 1) * 4;
    const uint32_t aQb = sm_addr(&sQ[(r0 + lrow)*68 + lcol4]);
    const uint32_t aPb = sm_addr(&sP[(r0 + lrow)*68 + lcol4]);
    uint32_t bKb[2];
    #pragma unroll
    for (int nt = 0; nt < 2; nt++)
        bKb[nt] = sm_addr(&sK[(wq*16 + nt*8 + (lane & 7))*68 + bcol4]);

    const int rA = r0 + g, rB = rA + 8;

    float o[18][4];
    #pragma unroll
    for (int nt = 0; nt < 18; nt++)
        #pragma unroll
        for (int c = 0; c < 4; c++) o[nt][c] = 0.f;

    const int nJT = bx + 1;
    for (int jt = 0; jt < nJT; jt++) {
        __syncthreads();
        const int jb = b * SEQ + jt * 64;
        #pragma unroll
        for (int u = 0; u < 2; u++) {
            int e = tid + (u << 9);
            int rr = e >> 4, d4 = e & 15;
            *(float4*)&sK[rr*68 + d4*4] =
                f4_tf32(*(const float4*)(g_proj + (size_t)(jb+rr)*NC + COL_KA + h*64 + d4*4));
        }
        for (int e = tid; e < 64 * 146; e += 512) {
            int rr = e / 146, c4 = e - rr * 146;
            float4 v;
            if (c4 < 16)
                v = *(const float4*)(g_sv + (size_t)(jb+rr)*512 + h*64 + c4*4);
            else
                v = *(const float4*)(g_proj + (size_t)(jb+rr)*NC + COL_KR + (c4-16)*4);
            *(float4*)&sV[rr*584 + c4*4] = f4_tf32(v);
        }
        __syncthreads();

        // ---- S: each warp m16 x n16 ----
        float c_[2][4];
        #pragma unroll
        for (int nt = 0; nt < 2; nt++)
            #pragma unroll
            for (int q = 0; q < 4; q++) c_[nt][q] = 0.f;
        #pragma unroll
        for (int ks = 0; ks < 8; ks++) {
            uint32_t a4[4];
            ldsm4(a4, aQb + ks * 32);
            #pragma unroll
            for (int nt = 0; nt < 2; nt++) {
                uint32_t b2[2];
                ldsm2(b2, bKb[nt] + ks * 32);
                mma_tf32u(c_[nt], a4, b2);
            }
        }
        const int rowA = i0 + rA, rowB = i0 + rB;
        float rmA = -1e30f, rmB = -1e30f;
        #pragma unroll
        for (int nt = 0; nt < 2; nt++) {
            int col = jt*64 + wq*16 + nt*8 + tig*2;
            c_[nt][0] = (col     <= rowA) ? c_[nt][0]*0.125f : -1e30f;
            c_[nt][1] = (col + 1 <= rowA) ? c_[nt][1]*0.125f : -1e30f;
            c_[nt][2] = (col     <= rowB) ? c_[nt][2]*0.125f : -1e30f;
            c_[nt][3] = (col + 1 <= rowB) ? c_[nt][3]*0.125f : -1e30f;
            rmA = fmaxf(rmA, fmaxf(c_[nt][0], c_[nt][1]));
            rmB = fmaxf(rmB, fmaxf(c_[nt][2], c_[nt][3]));
        }
        rmA = fmaxf(rmA, __shfl_xor_sync(0xffffffffu, rmA, 1));
        rmA = fmaxf(rmA, __shfl_xor_sync(0xffffffffu, rmA, 2));
        rmB = fmaxf(rmB, __shfl_xor_sync(0xffffffffu, rmB, 1));
        rmB = fmaxf(rmB, __shfl_xor_sync(0xffffffffu, rmB, 2));
        if (tig == 0) { sMaxP[wq*64 + rA] = rmA; sMaxP[wq*64 + rB] = rmB; }
        __syncthreads();

        float newmA = sM[rA], newmB = sM[rB];
        #pragma unroll
        for (int q2 = 0; q2 < 4; q2++) {
            newmA = fmaxf(newmA, sMaxP[q2*64 + rA]);
            newmB = fmaxf(newmB, sMaxP[q2*64 + rB]);
        }
        float corrA = __expf(sM[rA] - newmA);
        float corrB = __expf(sM[rB] - newmB);
        float sAcc = 0.f, sBcc = 0.f;
        #pragma unroll
        for (int nt = 0; nt < 2; nt++) {
            float p0 = __expf(c_[nt][0] - newmA);
            float p1 = __expf(c_[nt][1] - newmA);
            float p2 = __expf(c_[nt][2] - newmB);
            float p3 = __expf(c_[nt][3] - newmB);
            sAcc += p0 + p1; sBcc += p2 + p3;
            *(float2*)&sP[rA*68 + wq*16 + nt*8 + tig*2] = make_float2(to_tf32(p0), to_tf32(p1));
            *(float2*)&sP[rB*68 + wq*16 + nt*8 + tig*2] = make_float2(to_tf32(p2), to_tf32(p3));
        }
        sAcc += __shfl_xor_sync(0xffffffffu, sAcc, 1);
        sAcc += __shfl_xor_sync(0xffffffffu, sAcc, 2);
        sBcc += __shfl_xor_sync(0xffffffffu, sBcc, 1);
        sBcc += __shfl_xor_sync(0xffffffffu, sBcc, 2);
        if (tig == 0) { sSumP[wq*64 + rA] = sAcc; sSumP[wq*64 + rB] = sBcc; }
        if (wq == 0 && tig == 0) { sCorr[rA] = corrA; sCorr[rB] = corrB; }
        __syncthreads();

        if (wq == 0 && tig == 0) {
            float la = sL[rA]*corrA, lb = sL[rB]*corrB;
            #pragma unroll
            for (int q2 = 0; q2 < 4; q2++) {
                la += sSumP[q2*64 + rA];
                lb += sSumP[q2*64 + rB];
            }
            sM[rA] = newmA; sL[rA] = la;
            sM[rB] = newmB; sL[rB] = lb;
        }

        // ---- PV: warp (wband rows, wq 144-col d-quarter) ----
        {
            float cA = sCorr[rA], cB = sCorr[rB];
            #pragma unroll
            for (int nt = 0; nt < 18; nt++) {
                o[nt][0] *= cA; o[nt][1] *= cA;
                o[nt][2] *= cB; o[nt][3] *= cB;
            }
        }
        #pragma unroll
        for (int ks = 0; ks < 8; ks++) {
            uint32_t a4[4];
            ldsm4(a4, aPb + ks * 32);
            const int kc = ks*8 + tig;
            #pragma unroll
            for (int nt = 0; nt < 18; nt++) {
                const int n_ = wq*144 + nt*8 + g;
                uint32_t b2[2];
                b2[0] = __float_as_uint(sV[kc*584 + n_]);
                b2[1] = __float_as_uint(sV[(kc+4)*584 + n_]);
                mma_tf32u(o[nt], a4, b2);
            }
        }
    }

    __syncthreads();
    {
        const float invA = 1.f / sL[rA];
        const float invB = 1.f / sL[rB];
        const size_t akBase = ((size_t)blockIdx.y * SEQ + i0);
        #pragma unroll
        for (int nt = 0; nt < 18; nt++) {
            int col = wq*144 + nt*8 + tig*2;
            float2 vA = make_float2(o[nt][0]*invA, o[nt][1]*invA);
            float2 vB = make_float2(o[nt][2]*invB, o[nt][3]*invB);
            if (col < 64) {
                *(float2*)&g_ra[(size_t)(tbase+rA)*512 + h*64 + col] = vA;
                *(float2*)&g_ra[(size_t)(tbase+rB)*512 + h*64 + col] = vB;
            } else {
                *(float2*)&g_attkr[(akBase + rA)*512 + col - 64] = vA;
                *(float2*)&g_attkr[(akBase + rB)*512 + col - 64] = vB;
            }
        }
    }
}

// ---------------------------------------------------------------------------
// ra_post (unchanged): rel epilogue via wr into g_ra.
// ---------------------------------------------------------------------------
__global__ void __launch_bounds__(256) ra_post(const float* __restrict__ wr)
{
    const int lane = threadIdx.x & 31;
    const int wid  = threadIdx.x >> 5;
    const int job  = blockIdx.x * 8 + wid;
    const int h     = job & 7;
    const int token = job >> 3;
    const int bb    = token >> 11;
    const int ii    = token & (SEQ - 1);

    const int r = lane >> 2, q = lane & 3;
    const float* qr = g_proj + (size_t)token * NC + COL_QR;
    const float* ak = g_attkr + (((size_t)(bb*8 + h)) * SEQ + ii) * 512;

    float part = 0.f;
    #pragma unroll
    for (int u = 0; u < 4; u++) {
        float4 qv = *(const float4*)(qr + r*64 + q*16 + u*4);
        float4 av = *(const float4*)(ak + r*64 + q*16 + u*4);
        part += qv.x*av.x + qv.y*av.y + qv.z*av.z + qv.w*av.w;
    }
    part += __shfl_xor_sync(0xffffffffu, part, 1);
    part += __shfl_xor_sync(0xffffffffu, part, 2);
    part *= 0.125f;

    float pr[8];
    #pragma unroll
    for (int r2 = 0; r2 < 8; r2++)
        pr[r2] = __shfl_sync(0xffffffffu, part, r2 << 2);

    const float* wrh = wr + h * 512;
    float* dst = g_ra + (size_t)token * 512 + h * 64;
    #pragma unroll
    for (int dd = 0; dd < 2; dd++) {
        int d = lane * 2 + dd;
        float ro = 0.f;
        #pragma unroll
        for (int r2 = 0; r2 < 8; r2++)
            ro += pr[r2] * wrh[d*8 + r2];
        dst[d] += ro;
    }
}

// ---------------------------------------------------------------------------
extern "C" void kernel_launch(void* const* d_in, const int* in_sizes, int n_in,
                              void* d_out, int out_size)
{
    (void)in_sizes; (void)n_in; (void)out_size;
    const float* x      = (const float*)d_in[0];
    const float* symb   = (const float*)d_in[1];
    const float* fc     = (const float*)d_in[2];
    const float* fs     = (const float*)d_in[3];
    const float* wq_sa  = (const float*)d_in[4];
    const float* wk_sa  = (const float*)d_in[5];
    const float* wv_sa  = (const float*)d_in[6];
    const float* wo_sa  = (const float*)d_in[7];
    const float* wq_at  = (const float*)d_in[8];
    const float* wk_at  = (const float*)d_in[9];
    const float* wq_rel = (const float*)d_in[10];
    const float* wk_rel = (const float*)d_in[11];
    const float* wr     = (const float*)d_in[12];
    const float* wv_ra  = (const float*)d_in[13];
    const float* wo_ra  = (const float*)d_in[14];
    float* out = (float*)d_out;

    float *proj, *svb, *sab, *rab;
    cudaGetSymbolAddress((void**)&proj, g_proj);
    cudaGetSymbolAddress((void**)&svb,  g_sv);
    cudaGetSymbolAddress((void**)&sab,  g_sa);
    cudaGetSymbolAddress((void**)&rab,  g_ra);

    cudaFuncSetAttribute(sa_flash4, cudaFuncAttributeMaxDynamicSharedMemorySize, SA4_SMEM);
    cudaFuncSetAttribute(ra_flash4, cudaFuncAttributeMaxDynamicSharedMemorySize, RA4_SMEM);

    // 1) fused projections of x
    W8 w7;
    w7.p[0] = wq_sa; w7.p[1] = wk_sa; w7.p[2] = wv_sa;
    w7.p[3] = wq_at; w7.p[4] = wk_at; w7.p[5] = wq_rel; w7.p[6] = wk_rel;
    gemm_tf32<<<dim3(NC / 128, NTOK / 128), 256>>>(x, w7, proj, DM, NC, 0);

    // 2) sv = symbols @ wv_ra^T
    W8 wv; for (int i = 0; i < 7; i++) wv.p[i] = wv_ra;
    gemm_tf32<<<dim3(4, NTOK / 128), 256>>>(symb, wv, svb, DM, 512, 0);

    // 3) RoPE
    rope_kernel<<<(NTOK * 1024) / 256, 256>>>(fc, fs);

    // 4) SA flash (tensor core, all-warp S)
    sa_flash4<<<dim3(SEQ / 64, BATCH * 8), 256, SA4_SMEM>>>();

    // 5) RA flash + rel post pass
    ra_flash4<<<dim3(SEQ / 64, BATCH * 8), 512, RA4_SMEM>>>();
    ra_post<<<NTOK, 256>>>(wr);

    // 6) output projections
    W8 wo1; for (int i = 0; i < 7; i++) wo1.p[i] = wo_sa;
    gemm_tf32<<<dim3(4, NTOK / 128), 256>>>(sab, wo1, out, 512, 1024, 0);
    W8 wo2; for (int i = 0; i < 7; i++) wo2.p[i] = wo_ra;
    gemm_tf32<<<dim3(4, NTOK / 128), 256>>>(rab, wo2, out, 512, 1024, 512);
}